// round 7
// baseline (speedup 1.0000x reference)
#include <cuda_runtime.h>
#include <math.h>

#define T_DATA 20000
#define SUB 16
#define TNO 200
#define ENO 2000
#define INO 500
#define CHUNK 32
#define NCHUNK (T_DATA / CHUNK)
#define PI_F 3.14159265358979323846f

// ---------------- device scratch (no allocs allowed) ----------------
__device__ float g_syn_e[T_DATA * SUB];
__device__ float g_syn_i[T_DATA * SUB];
__device__ float g_base[T_DATA * SUB];
__device__ float g_ekT[TNO * SUB];   // [j][s]
__device__ float g_ikT[TNO * SUB];   // [j][s]
__device__ float g_hkT[TNO * SUB];   // [j][s] hist kernel
__device__ unsigned char g_seg_e[ENO];
__device__ unsigned char g_seg_i[INO];
__device__ float g_cw[SUB * SUB];    // C_den[s][q] * exp(W_spk[q]) / tau[q]
__device__ float g_rho[SUB];
__device__ int   g_fast;

// ---------------- K0: setup ----------------
__global__ void k_setup(const float* C_den, const float* C_syn_e, const float* C_syn_i,
                        const float* Tau_e, const float* Tau_i,
                        const float* W_e, const float* W_i,
                        const float* D_e, const float* D_i,
                        const float* Tau_spk, const float* W_spk,
                        const float* W_hist, float* out_filters)
{
    int tid = threadIdx.x;
    for (int idx = tid; idx < SUB * TNO; idx += blockDim.x) {
        int s = idx / TNO, j = idx % TNO;
        float t = (float)j;
        float te  = fmaxf(t - expf(D_e[s]), 0.f);
        float tte = te / expf(Tau_e[s]);
        float ek  = tte * expf(-tte) * expf(W_e[s]);
        float ti  = fmaxf(t - expf(D_i[s]), 0.f);
        float tti = ti / expf(Tau_i[s]);
        float ik  = -tti * expf(-tti) * expf(W_i[s]);
        float tts = t / expf(Tau_spk[s]);
        float sk  = tts * expf(-tts) * expf(W_spk[s]);
        float raw = 4.0f * logf(t + 1.0f);
        float hk = 0.f;
        for (int b = 0; b < 16; b++) {
            float phi = PI_F * 0.5f * (float)b;
            float v = 0.f;
            if (!(raw < phi - PI_F || raw > phi + PI_F))
                v = 0.5f * cosf(raw - phi) + 0.5f;
            hk += W_hist[s * 16 + b] * v;
        }
        g_ekT[j * SUB + s] = ek;
        g_ikT[j * SUB + s] = ik;
        g_hkT[j * SUB + s] = hk;
        out_filters[(0  + s) * TNO + j] = ek;
        out_filters[(16 + s) * TNO + j] = ik;
        out_filters[(32 + s) * TNO + j] = sk;
        out_filters[(48 + s) * TNO + j] = hk;
    }
    for (int e = tid; e < ENO; e += blockDim.x) {
        int seg = 0;
        for (int s = 0; s < SUB; s++) if (C_syn_e[s * ENO + e] > 0.5f) seg = s;
        g_seg_e[e] = (unsigned char)seg;
    }
    for (int e = tid; e < INO; e += blockDim.x) {
        int seg = 0;
        for (int s = 0; s < SUB; s++) if (C_syn_i[s * INO + e] > 0.5f) seg = s;
        g_seg_i[e] = (unsigned char)seg;
    }
    if (tid < SUB) g_rho[tid] = expf(-1.0f / expf(Tau_spk[tid]));
    if (tid < SUB * SUB) {
        int s = tid >> 4, q = tid & 15;
        g_cw[s * SUB + q] = C_den[s * SUB + q] * expf(W_spk[q]) / expf(Tau_spk[q]);
    }
    __syncthreads();
    if (tid == 0) {
        int fast = 1;
        float r0 = g_rho[0];
        for (int s = 1; s < SUB; s++) if (g_rho[s] != r0) fast = 0;
        g_fast = fast;
    }
}

// ---------------- K1: segment sums ----------------
#define SEG_ROWS 4
__global__ void k_segsum(const float* __restrict__ S_e, const float* __restrict__ S_i)
{
    __shared__ unsigned char sege[ENO];
    __shared__ unsigned char segi[INO];
    __shared__ float acc[SEG_ROWS][32];
    int tid = threadIdx.x;
    for (int e = tid; e < ENO; e += blockDim.x) sege[e] = g_seg_e[e];
    for (int e = tid; e < INO; e += blockDim.x) segi[e] = g_seg_i[e];
    if (tid < SEG_ROWS * 32) ((float*)acc)[tid] = 0.f;
    __syncthreads();
    int t0 = blockIdx.x * SEG_ROWS;
    for (int r = 0; r < SEG_ROWS; r++) {
        const float* re = S_e + (size_t)(t0 + r) * ENO;
        for (int e = tid; e < ENO; e += blockDim.x) {
            float v = re[e];
            if (v != 0.f) atomicAdd(&acc[r][sege[e]], v);
        }
        const float* ri = S_i + (size_t)(t0 + r) * INO;
        for (int e = tid; e < INO; e += blockDim.x) {
            float v = ri[e];
            if (v != 0.f) atomicAdd(&acc[r][16 + segi[e]], v);
        }
    }
    __syncthreads();
    if (tid < SEG_ROWS * 32) {
        int r = tid >> 5, q = tid & 31;
        if (q < 16) g_syn_e[(t0 + r) * SUB + q] = acc[r][q];
        else        g_syn_i[(t0 + r) * SUB + (q - 16)] = acc[r][q];
    }
}

// ---------------- K2: causal depthwise FIR + Theta -> base ----------------
#define TILE_T 128
__global__ void k_conv(const float* __restrict__ Theta)
{
    __shared__ float se[(TILE_T + TNO) * SUB];
    __shared__ float si[(TILE_T + TNO) * SUB];
    int t0 = blockIdx.x * TILE_T;
    int tid = threadIdx.x;
    for (int idx = tid; idx < 327 * SUB; idx += blockDim.x) {
        int r = idx / SUB, s = idx % SUB;
        int tt = t0 - 200 + r;
        float ve = 0.f, vi = 0.f;
        if (tt >= 0 && tt < T_DATA) {
            ve = g_syn_e[tt * SUB + s];
            vi = g_syn_i[tt * SUB + s];
        }
        se[idx] = ve;
        si[idx] = vi;
    }
    __syncthreads();
    int s = tid & 15, tg = tid >> 4;
    float th = Theta[s];
    float acc[8];
#pragma unroll
    for (int k = 0; k < 8; k++) acc[k] = th;
    for (int j = 0; j < TNO; j++) {
        float ke = g_ekT[j * SUB + s];
        float ki = g_ikT[j * SUB + s];
#pragma unroll
        for (int k = 0; k < 8; k++) {
            int tl = tg + k * 16;
            int row = tl + 199 - j;
            acc[k] += ke * se[row * SUB + s] + ki * si[row * SUB + s];
        }
    }
#pragma unroll
    for (int k = 0; k < 8; k++) {
        int t = t0 + tg + k * 16;
        if (t < T_DATA) g_base[t * SUB + s] = acc[k];
    }
}

// ---------------- K3: chunked scan — flag-chained 2-step wavefront ----------------
__global__ void __launch_bounds__(512, 1) k_scan(float* __restrict__ spk_out)
{
    __shared__ float k_sh[TNO * SUB];       // hist kernel [j][s]
    __shared__ unsigned ring[16 * SUB];     // spike bits: word w bit b = spike(32w+b)
    __shared__ float spf[CHUNK * SUB];      // (fallback path)
    __shared__ float inj_sh[CHUNK * SUB];   // per-step C_den injection
    __shared__ float P_sh[CHUNK * SUB];     // (fallback path)
    __shared__ float base_sh[CHUNK * SUB];  // (fallback path)
    __shared__ unsigned balw[16];           // per-round ballot words (stepA | stepB<<16)
    __shared__ float lut[4][16][16];        // nibble LUT: inj[s] from 4-bit spike groups
    __shared__ float Kpre_sh[CHUNK * SUB];  // prefix sums of k (fallback path)
    __shared__ float Ksuf_sh[CHUNK * SUB];  // suffix sums of k (pre-phase)
    __shared__ float cw_sh[SUB * 17];
    __shared__ float rho_sh[SUB];
    __shared__ float MA0[SUB], MB0[SUB];
    __shared__ float powt[CHUNK + 1], wt[CHUNK + 1];
    __shared__ float k0_sh[SUB];
    __shared__ int fast_sh;
    __shared__ int done_flag;               // monotonic: c*16 + rounds completed

    int tid = threadIdx.x;
    int wid = tid >> 5, lane = tid & 31;
    for (int idx = tid; idx < TNO * SUB; idx += 512) k_sh[idx] = g_hkT[idx];
    if (tid < 256) {
        int s = tid >> 4, q = tid & 15;
        cw_sh[s * 17 + q] = g_cw[s * SUB + q];
        ring[tid] = 0u;
    }
    if (tid < SUB) {
        rho_sh[tid] = g_rho[tid];
        MA0[tid] = 0.f; MB0[tid] = 0.f;
        k0_sh[tid] = g_hkT[0 * SUB + tid];
    }
    if (tid == 0) { fast_sh = g_fast; done_flag = 0; }
    spf[tid] = 0.f;
    __syncthreads();
    if (tid <= CHUNK) {
        float p = powf(rho_sh[0], (float)tid);
        powt[tid] = p;
        wt[tid] = (float)tid * p;
    }
    {
        int ii = tid >> 4, ss = tid & 15;
        float pre = 0.f;
        for (int b = 0; b < ii; b++) pre += k_sh[b * SUB + ss];
        float suf = 0.f;
        for (int b = ii; b < TNO; b++) suf += k_sh[b * SUB + ss];
        Kpre_sh[ii * SUB + ss] = pre;
        Ksuf_sh[ii * SUB + ss] = suf;
    }
    // nibble LUTs: lut[n][m][s] = sum over bits b of m of cw[s][4n+b]
    for (int idx = tid; idx < 1024; idx += 512) {
        int n = idx >> 8, m = (idx >> 4) & 15, ss = idx & 15;
        float v = 0.f;
        for (int b = 0; b < 4; b++)
            if ((m >> b) & 1) v += cw_sh[ss * 17 + 4 * n + b];
        lut[n][m][ss] = v;
    }
    __syncthreads();

    // fallback-path state
    float MBr = 0.f, A = 0.f, B = 0.f;
    float cwrow[16];
    if (tid < 16) {
#pragma unroll
        for (int q = 0; q < 16; q++) cwrow[q] = cw_sh[tid * 17 + q];
    }
    const int i = tid >> 4, s = tid & 15;

    // prefetch first chunk's base
    float basev = g_base[i * SUB + s];

    for (int c = 0; c < NCHUNK; c++) {
        int t0 = c * CHUNK;
        int fbase = c * 16;
        // ---- parallel pre-phase: P = sum over pre-chunk spikes of k[age] ----
        float P = 0.f;
        {
            int t = t0 + i;
            int uhi = t0 - 1;
            int ulo = t - TNO; if (ulo < 0) ulo = 0;
            if (uhi >= ulo) {
                int wlo = ulo >> 5;
                unsigned wv[8], vv[8];
                int ones = 0, span = 0;
#pragma unroll
                for (int q8 = 0; q8 < 8; q8++) {
                    int w = wlo + q8;
                    int bu = w << 5;
                    unsigned valid = 0u;
                    if (bu <= uhi) {
                        valid = 0xFFFFFFFFu;
                        if (bu < ulo) valid <<= (ulo - bu);
                        int hb = uhi - bu;
                        if (hb < 31) valid &= ((2u << hb) - 1u);
                    }
                    unsigned word = valid ? ring[(w & 15) * SUB + s] : 0u;
                    wv[q8] = word & valid;
                    vv[q8] = valid;
                    ones += __popc(wv[q8]);
                    span += __popc(valid);
                }
                if ((t >= TNO) && (2 * ones > span)) {
                    float a0 = 0.f, a1 = 0.f;
#pragma unroll
                    for (int q8 = 0; q8 < 8; q8++) {
                        unsigned zm = wv[q8] ^ vv[q8];
                        int Cw = t - 1 - ((wlo + q8) << 5);
                        while (zm) {
                            int b = __ffs(zm) - 1; zm &= zm - 1u;
                            a0 += k_sh[(Cw - b) * SUB + s];
                            if (zm) {
                                b = __ffs(zm) - 1; zm &= zm - 1u;
                                a1 += k_sh[(Cw - b) * SUB + s];
                            }
                        }
                    }
                    P = Ksuf_sh[i * SUB + s] - a0 - a1;
                } else {
                    float a0 = 0.f, a1 = 0.f;
#pragma unroll
                    for (int q8 = 0; q8 < 8; q8++) {
                        unsigned om = wv[q8];
                        int Cw = t - 1 - ((wlo + q8) << 5);
                        while (om) {
                            int b = __ffs(om) - 1; om &= om - 1u;
                            a0 += k_sh[(Cw - b) * SUB + s];
                            if (om) {
                                b = __ffs(om) - 1; om &= om - 1u;
                                a1 += k_sh[(Cw - b) * SUB + s];
                            }
                        }
                    }
                    P = a0 + a1;
                }
            }
        }

        if (fast_sh) {
            float bP = basev + P + powt[i] * MB0[s] + (float)i * powt[i] * MA0[s];
            float acc = 0.f;
            // ---- apply prior rounds as they become available (no block barrier) ----
            int applied = 0;
            while (applied < wid) {
                int f;
                do { f = *(volatile int*)&done_flag; } while (f < fbase + applied + 1);
                __threadfence_block();
                int avail = f - fbase; if (avail > wid) avail = wid;
                while (applied < avail) {
                    int r = applied;
                    unsigned bw = balw[r];
                    int dA = i - 1 - 2 * r, dB = dA - 1;
                    float injA = inj_sh[(2 * r) * SUB + s];
                    float injB = inj_sh[(2 * r + 1) * SUB + s];
                    acc += (((bw >> s) & 1u) ? k_sh[dA * SUB + s] : 0.f)
                         + (((bw >> (16 + s)) & 1u) ? k_sh[dB * SUB + s] : 0.f)
                         + wt[dA] * injA + wt[dB] * injB;
                    applied++;
                }
            }
            // ---- active round: resolve steps 2*wid, 2*wid+1 ----
            float subA = bP + acc;
            bool pa = (lane < 16) && (subA > 0.f);
            unsigned balA = __ballot_sync(0xFFFFFFFFu, pa) & 0xFFFFu;
            float subB = subA + (((balA >> s) & 1u) ? k0_sh[s] : 0.f);
            bool pbv = (lane >= 16) && (subB > 0.f);
            unsigned balB = __ballot_sync(0xFFFFFFFFu, pbv) >> 16;
            unsigned mybal = (lane < 16) ? balA : balB;
            float inj = lut[0][mybal & 15][s] + lut[1][(mybal >> 4) & 15][s]
                      + lut[2][(mybal >> 8) & 15][s] + lut[3][(mybal >> 12) & 15][s];
            inj_sh[i * SUB + s] = inj;
            if (lane == 0) balw[wid] = balA | (balB << 16);
            __threadfence_block();
            if (lane == 0) *(volatile int*)&done_flag = fbase + wid + 1;
            // direct output write (no smem round-trip)
            spk_out[(t0 + i) * SUB + s] = ((mybal >> s) & 1u) ? 1.f : 0.f;

            // ---- epilogue: warp 15 (last producer) updates carried state + ring ----
            if (wid == 15 && lane < 16) {
                float sA = 0.f, sB = 0.f;
                for (int u = 0; u < CHUNK; u++) {
                    float v = inj_sh[u * SUB + lane];
                    sA += powt[31 - u] * v;
                    sB += wt[31 - u] * v;
                }
                unsigned wbits = 0u;
                for (int r = 0; r < 16; r++) {
                    unsigned bw = balw[r];
                    wbits |= ((bw >> lane) & 1u) << (2 * r);
                    wbits |= ((bw >> (16 + lane)) & 1u) << (2 * r + 1);
                }
                float p32 = powt[CHUNK];
                float nMA = p32 * MA0[lane] + sA;
                float nMB = p32 * MB0[lane] + 32.f * p32 * MA0[lane] + sB;
                MA0[lane] = nMA;
                MB0[lane] = nMB;
                ring[((t0 >> 5) & 15) * SUB + lane] = wbits;
            }
            // prefetch next chunk's base before the chunk barrier
            float nextbase = 0.f;
            if (c + 1 < NCHUNK) nextbase = g_base[(t0 + CHUNK + i) * SUB + s];
            __syncthreads();   // one barrier per chunk: fences smem reuse + state updates
            basev = nextbase;
        } else {
            // ---- general fallback: serial loop (non-uniform rho) ----
            P_sh[tid] = P;
            base_sh[tid] = basev;
            __syncthreads();
            if (tid < 16) {
                int ss = tid;
                unsigned myhist = 0u;
                float rho_s = rho_sh[ss];
                for (int ii = 0; ii < CHUNK; ii++) {
                    float Pv = P_sh[ii * SUB + ss];
                    float bv = base_sh[ii * SUB + ss];
                    unsigned m = ii ? ((1u << ii) - 1u) : 0u;
                    unsigned om = myhist & m;
                    float intra;
                    if (2 * __popc(om) > ii) {
                        unsigned zm = om ^ m;
                        float a = 0.f;
                        while (zm) { int b = __ffs(zm) - 1; zm &= zm - 1u; a += k_sh[b * SUB + ss]; }
                        intra = Kpre_sh[ii * SUB + ss] - a;
                    } else {
                        float a = 0.f;
                        while (om) { int b = __ffs(om) - 1; om &= om - 1u; a += k_sh[b * SUB + ss]; }
                        intra = a;
                    }
                    float sub = bv + Pv + intra + MBr;
                    bool sp = sub > 0.f;
                    spf[ii * SUB + ss] = sp ? 1.f : 0.f;
                    myhist = (myhist << 1) | (sp ? 1u : 0u);
                    float Ao = A;
                    B = rho_s * (B + Ao);
                    A = rho_s * Ao + (sp ? 1.f : 0.f);
                    float accv = 0.f;
#pragma unroll
                    for (int q = 0; q < 16; q++)
                        accv += cwrow[q] * __shfl_sync(0x0000FFFFu, B, q);
                    MBr = accv;
                }
                ring[((t0 >> 5) & 15) * SUB + ss] = __brev(myhist);
            }
            __syncthreads();
            spk_out[t0 * SUB + tid] = spf[tid];
            float nextbase = 0.f;
            if (c + 1 < NCHUNK) nextbase = g_base[(t0 + CHUNK + i) * SUB + s];
            __syncthreads();
            basev = nextbase;
        }
    }
}

// ---------------- launch ----------------
extern "C" void kernel_launch(void* const* d_in, const int* in_sizes, int n_in,
                              void* d_out, int out_size)
{
    const float* S_e     = (const float*)d_in[0];
    const float* S_i     = (const float*)d_in[1];
    const float* C_den   = (const float*)d_in[2];
    const float* C_syn_e = (const float*)d_in[3];
    const float* C_syn_i = (const float*)d_in[4];
    const float* Tau_e   = (const float*)d_in[5];
    const float* Tau_i   = (const float*)d_in[6];
    const float* W_e     = (const float*)d_in[7];
    const float* W_i     = (const float*)d_in[8];
    const float* D_e     = (const float*)d_in[9];
    const float* D_i     = (const float*)d_in[10];
    const float* Tau_spk = (const float*)d_in[11];
    const float* W_spk   = (const float*)d_in[12];
    const float* W_hist  = (const float*)d_in[13];
    const float* Theta   = (const float*)d_in[14];
    float* out = (float*)d_out;
    float* out_filters = out + T_DATA * SUB;

    k_setup<<<1, 256>>>(C_den, C_syn_e, C_syn_i, Tau_e, Tau_i, W_e, W_i,
                        D_e, D_i, Tau_spk, W_spk, W_hist, out_filters);
    k_segsum<<<T_DATA / SEG_ROWS, 256>>>(S_e, S_i);
    k_conv<<<(T_DATA + TILE_T - 1) / TILE_T, 256>>>(Theta);
    k_scan<<<1, 512>>>(out);
}

// round 8
// speedup vs baseline: 1.0974x; 1.0974x over previous
#include <cuda_runtime.h>
#include <math.h>

#define T_DATA 20000
#define SUB 16
#define TNO 200
#define ENO 2000
#define INO 500
#define CHUNK 32
#define NCHUNK (T_DATA / CHUNK)
#define PI_F 3.14159265358979323846f

// ---------------- device scratch (no allocs allowed) ----------------
__device__ float g_syn_e[T_DATA * SUB];
__device__ float g_syn_i[T_DATA * SUB];
__device__ float g_base[T_DATA * SUB];
__device__ float g_ekT[TNO * SUB];   // [j][s]
__device__ float g_ikT[TNO * SUB];   // [j][s]
__device__ float g_hkT[TNO * SUB];   // [j][s] hist kernel
__device__ unsigned char g_seg_e[ENO];
__device__ unsigned char g_seg_i[INO];
__device__ float g_cw[SUB * SUB];    // C_den[s][q] * exp(W_spk[q]) / tau[q]
__device__ float g_rho[SUB];
__device__ int   g_fast;

#define PAIR_BAR(id) asm volatile("bar.sync %0, %1;" :: "r"(id), "r"(64) : "memory")

// ---------------- K0: setup ----------------
__global__ void k_setup(const float* C_den, const float* C_syn_e, const float* C_syn_i,
                        const float* Tau_e, const float* Tau_i,
                        const float* W_e, const float* W_i,
                        const float* D_e, const float* D_i,
                        const float* Tau_spk, const float* W_spk,
                        const float* W_hist, float* out_filters)
{
    int tid = threadIdx.x;
    for (int idx = tid; idx < SUB * TNO; idx += blockDim.x) {
        int s = idx / TNO, j = idx % TNO;
        float t = (float)j;
        float te  = fmaxf(t - expf(D_e[s]), 0.f);
        float tte = te / expf(Tau_e[s]);
        float ek  = tte * expf(-tte) * expf(W_e[s]);
        float ti  = fmaxf(t - expf(D_i[s]), 0.f);
        float tti = ti / expf(Tau_i[s]);
        float ik  = -tti * expf(-tti) * expf(W_i[s]);
        float tts = t / expf(Tau_spk[s]);
        float sk  = tts * expf(-tts) * expf(W_spk[s]);
        float raw = 4.0f * logf(t + 1.0f);
        float hk = 0.f;
        for (int b = 0; b < 16; b++) {
            float phi = PI_F * 0.5f * (float)b;
            float v = 0.f;
            if (!(raw < phi - PI_F || raw > phi + PI_F))
                v = 0.5f * cosf(raw - phi) + 0.5f;
            hk += W_hist[s * 16 + b] * v;
        }
        g_ekT[j * SUB + s] = ek;
        g_ikT[j * SUB + s] = ik;
        g_hkT[j * SUB + s] = hk;
        out_filters[(0  + s) * TNO + j] = ek;
        out_filters[(16 + s) * TNO + j] = ik;
        out_filters[(32 + s) * TNO + j] = sk;
        out_filters[(48 + s) * TNO + j] = hk;
    }
    for (int e = tid; e < ENO; e += blockDim.x) {
        int seg = 0;
        for (int s = 0; s < SUB; s++) if (C_syn_e[s * ENO + e] > 0.5f) seg = s;
        g_seg_e[e] = (unsigned char)seg;
    }
    for (int e = tid; e < INO; e += blockDim.x) {
        int seg = 0;
        for (int s = 0; s < SUB; s++) if (C_syn_i[s * INO + e] > 0.5f) seg = s;
        g_seg_i[e] = (unsigned char)seg;
    }
    if (tid < SUB) g_rho[tid] = expf(-1.0f / expf(Tau_spk[tid]));
    if (tid < SUB * SUB) {
        int s = tid >> 4, q = tid & 15;
        g_cw[s * SUB + q] = C_den[s * SUB + q] * expf(W_spk[q]) / expf(Tau_spk[q]);
    }
    __syncthreads();
    if (tid == 0) {
        int fast = 1;
        float r0 = g_rho[0];
        for (int s = 1; s < SUB; s++) if (g_rho[s] != r0) fast = 0;
        g_fast = fast;
    }
}

// ---------------- K1: segment sums ----------------
#define SEG_ROWS 4
__global__ void k_segsum(const float* __restrict__ S_e, const float* __restrict__ S_i)
{
    __shared__ unsigned char sege[ENO];
    __shared__ unsigned char segi[INO];
    __shared__ float acc[SEG_ROWS][32];
    int tid = threadIdx.x;
    for (int e = tid; e < ENO; e += blockDim.x) sege[e] = g_seg_e[e];
    for (int e = tid; e < INO; e += blockDim.x) segi[e] = g_seg_i[e];
    if (tid < SEG_ROWS * 32) ((float*)acc)[tid] = 0.f;
    __syncthreads();
    int t0 = blockIdx.x * SEG_ROWS;
    for (int r = 0; r < SEG_ROWS; r++) {
        const float* re = S_e + (size_t)(t0 + r) * ENO;
        for (int e = tid; e < ENO; e += blockDim.x) {
            float v = re[e];
            if (v != 0.f) atomicAdd(&acc[r][sege[e]], v);
        }
        const float* ri = S_i + (size_t)(t0 + r) * INO;
        for (int e = tid; e < INO; e += blockDim.x) {
            float v = ri[e];
            if (v != 0.f) atomicAdd(&acc[r][16 + segi[e]], v);
        }
    }
    __syncthreads();
    if (tid < SEG_ROWS * 32) {
        int r = tid >> 5, q = tid & 31;
        if (q < 16) g_syn_e[(t0 + r) * SUB + q] = acc[r][q];
        else        g_syn_i[(t0 + r) * SUB + (q - 16)] = acc[r][q];
    }
}

// ---------------- K2: causal depthwise FIR + Theta -> base ----------------
#define TILE_T 128
__global__ void k_conv(const float* __restrict__ Theta)
{
    __shared__ float se[(TILE_T + TNO) * SUB];
    __shared__ float si[(TILE_T + TNO) * SUB];
    int t0 = blockIdx.x * TILE_T;
    int tid = threadIdx.x;
    for (int idx = tid; idx < 327 * SUB; idx += blockDim.x) {
        int r = idx / SUB, s = idx % SUB;
        int tt = t0 - 200 + r;
        float ve = 0.f, vi = 0.f;
        if (tt >= 0 && tt < T_DATA) {
            ve = g_syn_e[tt * SUB + s];
            vi = g_syn_i[tt * SUB + s];
        }
        se[idx] = ve;
        si[idx] = vi;
    }
    __syncthreads();
    int s = tid & 15, tg = tid >> 4;
    float th = Theta[s];
    float acc[8];
#pragma unroll
    for (int k = 0; k < 8; k++) acc[k] = th;
    for (int j = 0; j < TNO; j++) {
        float ke = g_ekT[j * SUB + s];
        float ki = g_ikT[j * SUB + s];
#pragma unroll
        for (int k = 0; k < 8; k++) {
            int tl = tg + k * 16;
            int row = tl + 199 - j;
            acc[k] += ke * se[row * SUB + s] + ki * si[row * SUB + s];
        }
    }
#pragma unroll
    for (int k = 0; k < 8; k++) {
        int t = t0 + tg + k * 16;
        if (t < T_DATA) g_base[t * SUB + s] = acc[k];
    }
}

// ---------------- K3: chunked scan — pair-barrier wavefront + overlapped pre-phase ----------------
__global__ void __launch_bounds__(512, 1) k_scan(float* __restrict__ spk_out)
{
    __shared__ float k_sh[TNO * SUB];       // hist kernel [j][s]
    __shared__ unsigned ring[16 * SUB];     // spike bits: word w bit b = spike(32w+b)
    __shared__ float spf[CHUNK * SUB];      // (fallback path)
    __shared__ float inj_sh[CHUNK * SUB];   // per-step C_den injection
    __shared__ float P_sh[CHUNK * SUB];     // (fallback path)
    __shared__ float base_sh[CHUNK * SUB];  // (fallback path)
    __shared__ unsigned balw[16];           // per-round ballot words (stepA | stepB<<16)
    __shared__ float lut[4][16][16];        // nibble LUT: inj[s] from 4-bit spike groups
    __shared__ float Kpre_sh[CHUNK * SUB];  // prefix sums of k (fallback path)
    __shared__ float Ksuf_sh[CHUNK * SUB];  // Σ_{b>=i} k[b]
    __shared__ float Ksuf2_sh[CHUNK * SUB]; // Σ_{b>=i+32} k[b]
    __shared__ float Kseg_sh[CHUNK * SUB];  // Σ_{b=i..i+31} k[b]
    __shared__ float sApart[16 * SUB], sBpart[16 * SUB];
    __shared__ float cw_sh[SUB * 17];
    __shared__ float rho_sh[SUB];
    __shared__ float MA0[SUB], MB0[SUB];
    __shared__ float powt[CHUNK + 1], wt[CHUNK + 1];
    __shared__ float k0_sh[SUB];
    __shared__ int fast_sh;

    int tid = threadIdx.x;
    int wid = tid >> 5, lane = tid & 31;
    for (int idx = tid; idx < TNO * SUB; idx += 512) k_sh[idx] = g_hkT[idx];
    if (tid < 256) {
        int s = tid >> 4, q = tid & 15;
        cw_sh[s * 17 + q] = g_cw[s * SUB + q];
        ring[tid] = 0u;
    }
    if (tid < SUB) {
        rho_sh[tid] = g_rho[tid];
        MA0[tid] = 0.f; MB0[tid] = 0.f;
        k0_sh[tid] = g_hkT[0 * SUB + tid];
    }
    if (tid == 0) fast_sh = g_fast;
    spf[tid] = 0.f;
    __syncthreads();
    if (tid <= CHUNK) {
        float p = powf(rho_sh[0], (float)tid);
        powt[tid] = p;
        wt[tid] = (float)tid * p;
    }
    {
        int ii = tid >> 4, ss = tid & 15;
        float pre = 0.f;
        for (int b = 0; b < ii; b++) pre += k_sh[b * SUB + ss];
        float suf = 0.f;
        for (int b = ii; b < TNO; b++) suf += k_sh[b * SUB + ss];
        float suf2 = 0.f;
        for (int b = ii + 32; b < TNO; b++) suf2 += k_sh[b * SUB + ss];
        Kpre_sh[ii * SUB + ss] = pre;
        Ksuf_sh[ii * SUB + ss] = suf;
        Ksuf2_sh[ii * SUB + ss] = suf2;
        Kseg_sh[ii * SUB + ss] = suf - suf2;
    }
    for (int idx = tid; idx < 1024; idx += 512) {
        int n = idx >> 8, m = (idx >> 4) & 15, ss = idx & 15;
        float v = 0.f;
        for (int b = 0; b < 4; b++)
            if ((m >> b) & 1) v += cw_sh[ss * 17 + 4 * n + b];
        lut[n][m][ss] = v;
    }
    __syncthreads();

    // fallback-path state
    float MBr = 0.f, A = 0.f, B = 0.f;
    float cwrow[16];
    if (tid < 16) {
#pragma unroll
        for (int q = 0; q < 16; q++) cwrow[q] = cw_sh[tid * 17 + q];
    }
    const int i = tid >> 4, s = tid & 15;

    float basev = g_base[i * SUB + s];   // prefetch chunk 0
    float Pold = 0.f;                    // spikes from chunks <= c-2 (none for c=0)

    for (int c = 0; c < NCHUNK; c++) {
        int t0 = c * CHUNK;

        if (fast_sh) {
            // ---- P_cur: spikes of chunk c-1 (one ring word), adaptive ----
            float Pcur = 0.f;
            if (c > 0) {
                unsigned W = ring[((c - 1) & 15) * SUB + s];
                if (__popc(W) >= 16) {
                    float a = 0.f;
                    unsigned zm = ~W;
                    while (zm) { int u = __ffs(zm) - 1; zm &= zm - 1u; a += k_sh[(i + 31 - u) * SUB + s]; }
                    Pcur = Kseg_sh[i * SUB + s] - a;
                } else {
                    float a = 0.f;
                    unsigned om = W;
                    while (om) { int u = __ffs(om) - 1; om &= om - 1u; a += k_sh[(i + 31 - u) * SUB + s]; }
                    Pcur = a;
                }
            }
            float bP = basev + Pold + Pcur + powt[i] * MB0[s] + wt[i] * MA0[s];
            float acc = 0.f;

            // ---- wavefront: warp w resolves steps 2w, 2w+1 ----
            if (wid > 0) {
                PAIR_BAR(wid);              // wait for warp wid-1 (transitively all < wid)
                for (int r = 0; r < wid; r++) {
                    unsigned bw = balw[r];
                    int dA = i - 1 - 2 * r, dB = dA - 1;
                    acc += (((bw >> s) & 1u) ? k_sh[dA * SUB + s] : 0.f)
                         + (((bw >> (16 + s)) & 1u) ? k_sh[dB * SUB + s] : 0.f)
                         + wt[dA] * inj_sh[(2 * r) * SUB + s]
                         + wt[dB] * inj_sh[(2 * r + 1) * SUB + s];
                }
            } else if (lane < 16) {
                ring[((t0 >> 5) & 15) * SUB + lane] = 0u;   // zero this chunk's ring word
            }
            float subA = bP + acc;
            bool pa = (lane < 16) && (subA > 0.f);
            unsigned balA = __ballot_sync(0xFFFFFFFFu, pa) & 0xFFFFu;
            float subB = subA + (((balA >> s) & 1u) ? k0_sh[s] : 0.f);
            bool pbv = (lane >= 16) && (subB > 0.f);
            unsigned balB = __ballot_sync(0xFFFFFFFFu, pbv) >> 16;
            unsigned mybal = (lane < 16) ? balA : balB;
            float inj = lut[0][mybal & 15][s] + lut[1][(mybal >> 4) & 15][s]
                      + lut[2][(mybal >> 8) & 15][s] + lut[3][(mybal >> 12) & 15][s];
            inj_sh[i * SUB + s] = inj;
            if (lane == 0) balw[wid] = balA | (balB << 16);
            // per-warp state partials + ring bits (published before the pair barrier)
            float injB = __shfl_sync(0xFFFFFFFFu, inj, (lane & 15) + 16);
            float myA = 0.f, myB = 0.f;
            if (lane < 16) {
                myA = powt[31 - 2 * wid] * inj + powt[30 - 2 * wid] * injB;
                myB = wt[31 - 2 * wid] * inj + wt[30 - 2 * wid] * injB;
                if (wid < 15) { sApart[wid * SUB + s] = myA; sBpart[wid * SUB + s] = myB; }
                unsigned bits = (((balA >> s) & 1u) << (2 * wid)) | (((balB >> s) & 1u) << (2 * wid + 1));
                atomicOr(&ring[((t0 >> 5) & 15) * SUB + s], bits);
            }
            if (wid < 15) PAIR_BAR(wid + 1);   // release warp wid+1

            // off-critical-path work
            spk_out[(t0 + i) * SUB + s] = ((mybal >> s) & 1u) ? 1.f : 0.f;
            float nextbase = 0.f;
            if (c + 1 < NCHUNK) nextbase = g_base[(t0 + CHUNK + i) * SUB + s];

            if (wid == 15 && lane < 16) {
                float sA = myA, sB = myB;
                for (int r = 0; r < 15; r++) {
                    sA += sApart[r * SUB + lane];
                    sB += sBpart[r * SUB + lane];
                }
                float p32 = powt[CHUNK];
                float nMA = p32 * MA0[lane] + sA;
                float nMB = p32 * MB0[lane] + 32.f * p32 * MA0[lane] + sB;
                MA0[lane] = nMA;
                MB0[lane] = nMB;
            }

            // ---- P_old for chunk c+1: spikes at u in [t-200, 32c-1], overlapped ----
            float Pn = 0.f;
            if (c + 1 < NCHUNK) {
                int t = t0 + CHUNK + i;
                int uhi = t0 - 1;
                int ulo = t - TNO; if (ulo < 0) ulo = 0;
                if (uhi >= ulo) {
                    int wlo = ulo >> 5;
                    unsigned wv[6], vv[6];
                    int ones = 0, span = 0;
#pragma unroll
                    for (int q6 = 0; q6 < 6; q6++) {
                        int w = wlo + q6;
                        int bu = w << 5;
                        unsigned valid = 0u;
                        if (bu <= uhi) {
                            valid = 0xFFFFFFFFu;
                            if (bu < ulo) valid <<= (ulo - bu);
                            int hb = uhi - bu;
                            if (hb < 31) valid &= ((2u << hb) - 1u);
                        }
                        unsigned word = valid ? ring[(w & 15) * SUB + s] : 0u;
                        wv[q6] = word & valid;
                        vv[q6] = valid;
                        ones += __popc(wv[q6]);
                        span += __popc(valid);
                    }
                    if ((t >= TNO) && (2 * ones > span)) {
                        float a0 = 0.f, a1 = 0.f;
#pragma unroll
                        for (int q6 = 0; q6 < 6; q6++) {
                            unsigned zm = wv[q6] ^ vv[q6];
                            int Cw = t - 1 - ((wlo + q6) << 5);
                            while (zm) {
                                int b = __ffs(zm) - 1; zm &= zm - 1u;
                                a0 += k_sh[(Cw - b) * SUB + s];
                                if (zm) {
                                    b = __ffs(zm) - 1; zm &= zm - 1u;
                                    a1 += k_sh[(Cw - b) * SUB + s];
                                }
                            }
                        }
                        Pn = Ksuf2_sh[i * SUB + s] - a0 - a1;
                    } else {
                        float a0 = 0.f, a1 = 0.f;
#pragma unroll
                        for (int q6 = 0; q6 < 6; q6++) {
                            unsigned om = wv[q6];
                            int Cw = t - 1 - ((wlo + q6) << 5);
                            while (om) {
                                int b = __ffs(om) - 1; om &= om - 1u;
                                a0 += k_sh[(Cw - b) * SUB + s];
                                if (om) {
                                    b = __ffs(om) - 1; om &= om - 1u;
                                    a1 += k_sh[(Cw - b) * SUB + s];
                                }
                            }
                        }
                        Pn = a0 + a1;
                    }
                }
            }
            __syncthreads();    // one block barrier per chunk
            Pold = Pn;
            basev = nextbase;
        } else {
            // ---- general fallback: full pre-phase + serial loop (non-uniform rho) ----
            float P = 0.f;
            {
                int t = t0 + i;
                int uhi = t0 - 1;
                int ulo = t - TNO; if (ulo < 0) ulo = 0;
                if (uhi >= ulo) {
                    int wlo = ulo >> 5;
#pragma unroll
                    for (int q8 = 0; q8 < 8; q8++) {
                        int w = wlo + q8;
                        int bu = w << 5;
                        unsigned valid = 0u;
                        if (bu >= 0 && bu <= uhi) {
                            valid = 0xFFFFFFFFu;
                            if (bu < ulo) valid <<= (ulo - bu);
                            int hb = uhi - bu;
                            if (hb < 31) valid &= ((2u << hb) - 1u);
                        }
                        unsigned om = (valid ? ring[(w & 15) * SUB + s] : 0u) & valid;
                        int Cw = t - 1 - (w << 5);
                        while (om) {
                            int b = __ffs(om) - 1; om &= om - 1u;
                            P += k_sh[(Cw - b) * SUB + s];
                        }
                    }
                }
            }
            P_sh[tid] = P;
            base_sh[tid] = basev;
            __syncthreads();
            if (tid < 16) {
                int ss = tid;
                unsigned myhist = 0u;
                float rho_s = rho_sh[ss];
                for (int ii = 0; ii < CHUNK; ii++) {
                    float Pv = P_sh[ii * SUB + ss];
                    float bv = base_sh[ii * SUB + ss];
                    unsigned m = ii ? ((1u << ii) - 1u) : 0u;
                    unsigned om = myhist & m;
                    float intra;
                    if (2 * __popc(om) > ii) {
                        unsigned zm = om ^ m;
                        float a = 0.f;
                        while (zm) { int b = __ffs(zm) - 1; zm &= zm - 1u; a += k_sh[b * SUB + ss]; }
                        intra = Kpre_sh[ii * SUB + ss] - a;
                    } else {
                        float a = 0.f;
                        while (om) { int b = __ffs(om) - 1; om &= om - 1u; a += k_sh[b * SUB + ss]; }
                        intra = a;
                    }
                    float sub = bv + Pv + intra + MBr;
                    bool sp = sub > 0.f;
                    spf[ii * SUB + ss] = sp ? 1.f : 0.f;
                    myhist = (myhist << 1) | (sp ? 1u : 0u);
                    float Ao = A;
                    B = rho_s * (B + Ao);
                    A = rho_s * Ao + (sp ? 1.f : 0.f);
                    float accv = 0.f;
#pragma unroll
                    for (int q = 0; q < 16; q++)
                        accv += cwrow[q] * __shfl_sync(0x0000FFFFu, B, q);
                    MBr = accv;
                }
                ring[((t0 >> 5) & 15) * SUB + ss] = __brev(myhist);
            }
            __syncthreads();
            spk_out[t0 * SUB + tid] = spf[tid];
            float nextbase = 0.f;
            if (c + 1 < NCHUNK) nextbase = g_base[(t0 + CHUNK + i) * SUB + s];
            __syncthreads();
            basev = nextbase;
        }
    }
}

// ---------------- launch ----------------
extern "C" void kernel_launch(void* const* d_in, const int* in_sizes, int n_in,
                              void* d_out, int out_size)
{
    const float* S_e     = (const float*)d_in[0];
    const float* S_i     = (const float*)d_in[1];
    const float* C_den   = (const float*)d_in[2];
    const float* C_syn_e = (const float*)d_in[3];
    const float* C_syn_i = (const float*)d_in[4];
    const float* Tau_e   = (const float*)d_in[5];
    const float* Tau_i   = (const float*)d_in[6];
    const float* W_e     = (const float*)d_in[7];
    const float* W_i     = (const float*)d_in[8];
    const float* D_e     = (const float*)d_in[9];
    const float* D_i     = (const float*)d_in[10];
    const float* Tau_spk = (const float*)d_in[11];
    const float* W_spk   = (const float*)d_in[12];
    const float* W_hist  = (const float*)d_in[13];
    const float* Theta   = (const float*)d_in[14];
    float* out = (float*)d_out;
    float* out_filters = out + T_DATA * SUB;

    k_setup<<<1, 256>>>(C_den, C_syn_e, C_syn_i, Tau_e, Tau_i, W_e, W_i,
                        D_e, D_i, Tau_spk, W_spk, W_hist, out_filters);
    k_segsum<<<T_DATA / SEG_ROWS, 256>>>(S_e, S_i);
    k_conv<<<(T_DATA + TILE_T - 1) / TILE_T, 256>>>(Theta);
    k_scan<<<1, 512>>>(out);
}

// round 9
// speedup vs baseline: 2.0919x; 1.9062x over previous
#include <cuda_runtime.h>
#include <math.h>

#define T_DATA 20000
#define SUB 16
#define TNO 200
#define ENO 2000
#define INO 500
#define CHUNK 32
#define NCHUNK (T_DATA / CHUNK)
#define KSTR 17
#define PI_F 3.14159265358979323846f

// ---------------- device scratch (no allocs allowed) ----------------
__device__ float g_syn_e[T_DATA * SUB];
__device__ float g_syn_i[T_DATA * SUB];
__device__ float g_base[T_DATA * SUB];
__device__ float g_ekT[TNO * SUB];   // [j][s]
__device__ float g_ikT[TNO * SUB];   // [j][s]
__device__ float g_hkT[TNO * SUB];   // [j][s] hist kernel
__device__ unsigned char g_seg_e[ENO];
__device__ unsigned char g_seg_i[INO];
__device__ float g_cw[SUB * SUB];    // C_den[s][q] * exp(W_spk[q]) / tau[q]
__device__ float g_rho[SUB];
__device__ int   g_fast;

#define PAIR_BAR(id) asm volatile("bar.sync %0, %1;" :: "r"(id), "r"(64) : "memory")

// ---------------- K0: setup ----------------
__global__ void k_setup(const float* C_den, const float* C_syn_e, const float* C_syn_i,
                        const float* Tau_e, const float* Tau_i,
                        const float* W_e, const float* W_i,
                        const float* D_e, const float* D_i,
                        const float* Tau_spk, const float* W_spk,
                        const float* W_hist, float* out_filters)
{
    int tid = threadIdx.x;
    for (int idx = tid; idx < SUB * TNO; idx += blockDim.x) {
        int s = idx / TNO, j = idx % TNO;
        float t = (float)j;
        float te  = fmaxf(t - expf(D_e[s]), 0.f);
        float tte = te / expf(Tau_e[s]);
        float ek  = tte * expf(-tte) * expf(W_e[s]);
        float ti  = fmaxf(t - expf(D_i[s]), 0.f);
        float tti = ti / expf(Tau_i[s]);
        float ik  = -tti * expf(-tti) * expf(W_i[s]);
        float tts = t / expf(Tau_spk[s]);
        float sk  = tts * expf(-tts) * expf(W_spk[s]);
        float raw = 4.0f * logf(t + 1.0f);
        float hk = 0.f;
        for (int b = 0; b < 16; b++) {
            float phi = PI_F * 0.5f * (float)b;
            float v = 0.f;
            if (!(raw < phi - PI_F || raw > phi + PI_F))
                v = 0.5f * cosf(raw - phi) + 0.5f;
            hk += W_hist[s * 16 + b] * v;
        }
        g_ekT[j * SUB + s] = ek;
        g_ikT[j * SUB + s] = ik;
        g_hkT[j * SUB + s] = hk;
        out_filters[(0  + s) * TNO + j] = ek;
        out_filters[(16 + s) * TNO + j] = ik;
        out_filters[(32 + s) * TNO + j] = sk;
        out_filters[(48 + s) * TNO + j] = hk;
    }
    for (int e = tid; e < ENO; e += blockDim.x) {
        int seg = 0;
        for (int s = 0; s < SUB; s++) if (C_syn_e[s * ENO + e] > 0.5f) seg = s;
        g_seg_e[e] = (unsigned char)seg;
    }
    for (int e = tid; e < INO; e += blockDim.x) {
        int seg = 0;
        for (int s = 0; s < SUB; s++) if (C_syn_i[s * INO + e] > 0.5f) seg = s;
        g_seg_i[e] = (unsigned char)seg;
    }
    if (tid < SUB) g_rho[tid] = expf(-1.0f / expf(Tau_spk[tid]));
    if (tid < SUB * SUB) {
        int s = tid >> 4, q = tid & 15;
        g_cw[s * SUB + q] = C_den[s * SUB + q] * expf(W_spk[q]) / expf(Tau_spk[q]);
    }
    __syncthreads();
    if (tid == 0) {
        int fast = 1;
        float r0 = g_rho[0];
        for (int s = 1; s < SUB; s++) if (g_rho[s] != r0) fast = 0;
        g_fast = fast;
    }
}

// ---------------- K1: segment sums ----------------
#define SEG_ROWS 4
__global__ void k_segsum(const float* __restrict__ S_e, const float* __restrict__ S_i)
{
    __shared__ unsigned char sege[ENO];
    __shared__ unsigned char segi[INO];
    __shared__ float acc[SEG_ROWS][32];
    int tid = threadIdx.x;
    for (int e = tid; e < ENO; e += blockDim.x) sege[e] = g_seg_e[e];
    for (int e = tid; e < INO; e += blockDim.x) segi[e] = g_seg_i[e];
    if (tid < SEG_ROWS * 32) ((float*)acc)[tid] = 0.f;
    __syncthreads();
    int t0 = blockIdx.x * SEG_ROWS;
    for (int r = 0; r < SEG_ROWS; r++) {
        const float* re = S_e + (size_t)(t0 + r) * ENO;
        for (int e = tid; e < ENO; e += blockDim.x) {
            float v = re[e];
            if (v != 0.f) atomicAdd(&acc[r][sege[e]], v);
        }
        const float* ri = S_i + (size_t)(t0 + r) * INO;
        for (int e = tid; e < INO; e += blockDim.x) {
            float v = ri[e];
            if (v != 0.f) atomicAdd(&acc[r][16 + segi[e]], v);
        }
    }
    __syncthreads();
    if (tid < SEG_ROWS * 32) {
        int r = tid >> 5, q = tid & 31;
        if (q < 16) g_syn_e[(t0 + r) * SUB + q] = acc[r][q];
        else        g_syn_i[(t0 + r) * SUB + (q - 16)] = acc[r][q];
    }
}

// ---------------- K2: causal depthwise FIR + Theta -> base ----------------
#define TILE_T 128
__global__ void k_conv(const float* __restrict__ Theta)
{
    __shared__ float se[(TILE_T + TNO) * SUB];
    __shared__ float si[(TILE_T + TNO) * SUB];
    int t0 = blockIdx.x * TILE_T;
    int tid = threadIdx.x;
    for (int idx = tid; idx < 327 * SUB; idx += blockDim.x) {
        int r = idx / SUB, s = idx % SUB;
        int tt = t0 - 200 + r;
        float ve = 0.f, vi = 0.f;
        if (tt >= 0 && tt < T_DATA) {
            ve = g_syn_e[tt * SUB + s];
            vi = g_syn_i[tt * SUB + s];
        }
        se[idx] = ve;
        si[idx] = vi;
    }
    __syncthreads();
    int s = tid & 15, tg = tid >> 4;
    float th = Theta[s];
    float acc[8];
#pragma unroll
    for (int k = 0; k < 8; k++) acc[k] = th;
    for (int j = 0; j < TNO; j++) {
        float ke = g_ekT[j * SUB + s];
        float ki = g_ikT[j * SUB + s];
#pragma unroll
        for (int k = 0; k < 8; k++) {
            int tl = tg + k * 16;
            int row = tl + 199 - j;
            acc[k] += ke * se[row * SUB + s] + ki * si[row * SUB + s];
        }
    }
#pragma unroll
    for (int k = 0; k < 8; k++) {
        int t = t0 + tg + k * 16;
        if (t < T_DATA) g_base[t * SUB + s] = acc[k];
    }
}

// ---------------- K3: wavefront + warp-uniform diagonal history FIR ----------------
__global__ void __launch_bounds__(512, 1) k_scan(float* __restrict__ spk_out)
{
    __shared__ float kpad[256 * KSTR];      // zero-padded hist kernel [j][s], stride 17
    __shared__ unsigned ring[16 * SUB];     // spike bits: word w bit b = spike(32w+b)
    __shared__ float inj_sh[CHUNK * SUB];   // per-step C_den injection (current chunk)
    __shared__ unsigned balw[2][16];        // double-buffered per-round ballots
    __shared__ float lut[4][16][16];        // nibble LUT for inj
    __shared__ float S2_sh[32 * KSTR];      // Σ_{j>=i+32} k[j][s]
    __shared__ float Pn_sh[2][32 * KSTR];   // double-buffered next-chunk P
    __shared__ float sApart[16 * SUB], sBpart[16 * SUB];
    __shared__ float cw_sh[SUB * 17];
    __shared__ float rho_sh[SUB];
    __shared__ float MA0[SUB], MB0[SUB];
    __shared__ float powt[CHUNK + 1], wt[CHUNK + 1];
    __shared__ int fast_sh;
    // fallback-only buffers
    __shared__ float spf[CHUNK * SUB], P_sh[CHUNK * SUB], base_sh[CHUNK * SUB];
    __shared__ float Kpre_sh[32 * KSTR];

    int tid = threadIdx.x;
    int wid = tid >> 5, lane = tid & 31;

    // ---- init phase 1: zero kpad + Pn + balw + ring, load cw/rho ----
    for (int idx = tid; idx < 256 * KSTR; idx += 512) kpad[idx] = 0.f;
    for (int idx = tid; idx < 2 * 32 * KSTR; idx += 512) ((float*)Pn_sh)[idx] = 0.f;
    if (tid < 32) ((unsigned*)balw)[tid] = 0u;
    if (tid < 256) {
        int s = tid >> 4, q = tid & 15;
        cw_sh[s * 17 + q] = g_cw[s * SUB + q];
        ring[tid] = 0u;
    }
    if (tid < SUB) {
        rho_sh[tid] = g_rho[tid];
        MA0[tid] = 0.f; MB0[tid] = 0.f;
    }
    if (tid == 0) fast_sh = g_fast;
    __syncthreads();
    // ---- init phase 2: fill kpad, powt/wt ----
    for (int idx = tid; idx < TNO * SUB; idx += 512) {
        int j = idx >> 4, s = idx & 15;
        kpad[j * KSTR + s] = g_hkT[idx];
    }
    if (tid <= CHUNK) {
        float p = powf(rho_sh[0], (float)tid);
        powt[tid] = p;
        wt[tid] = (float)tid * p;
    }
    for (int idx = tid; idx < 1024; idx += 512) {
        int n = idx >> 8, m = (idx >> 4) & 15, ss = idx & 15;
        float v = 0.f;
        for (int b = 0; b < 4; b++)
            if ((m >> b) & 1) v += cw_sh[ss * 17 + 4 * n + b];
        lut[n][m][ss] = v;
    }
    __syncthreads();
    // ---- init phase 3: S2, Kpre (need kpad) ----
    {
        int ii = tid >> 4, ss = tid & 15;
        float suf = 0.f;
        for (int b = ii + 32; b < TNO; b++) suf += kpad[b * KSTR + ss];
        S2_sh[ii * KSTR + ss] = suf;
        float pre = 0.f;
        for (int b = 0; b < ii; b++) pre += kpad[b * KSTR + ss];
        Kpre_sh[ii * KSTR + ss] = pre;
    }
    __syncthreads();

    // fallback-path state
    float MBr = 0.f, A = 0.f, B = 0.f;
    float cwrow[16];
    if (tid < 16) {
#pragma unroll
        for (int q = 0; q < 16; q++) cwrow[q] = cw_sh[tid * 17 + q];
    }
    const int i = tid >> 4, s = tid & 15;
    float k0reg = kpad[s];                 // k[0][s]
    float basev = g_base[i * SUB + s];     // prefetch chunk 0

    for (int c = 0; c < NCHUNK; c++) {
        int t0 = c * CHUNK;

        if (fast_sh) {
            // ---- diagonal Pn closure (warp-uniform loops); warp wid handles s = wid ----
            auto computePn = [&]() -> float {
                unsigned W[6];
                int ones = 0;
                int wbase = c - 6;
#pragma unroll
                for (int q = 0; q < 6; q++) {
                    int w = wbase + q;
                    unsigned wd = (w >= 0) ? ring[(w & 15) * SUB + wid] : 0u;
                    W[q] = wd;
                    ones += __popc(wd);
                }
                float a0 = 0.f, a1 = 0.f;
                if (2 * ones > 192) {
#pragma unroll
                    for (int q = 0; q < 6; q++) {
                        unsigned zm = ~W[q];
                        int D0 = 223 - 32 * q + lane;
                        while (zm) {
                            int b = __ffs(zm) - 1; zm &= zm - 1u;
                            a0 += kpad[(D0 - b) * KSTR + wid];
                            if (zm) {
                                b = __ffs(zm) - 1; zm &= zm - 1u;
                                a1 += kpad[(D0 - b) * KSTR + wid];
                            }
                        }
                    }
                    return S2_sh[lane * KSTR + wid] - a0 - a1;
                } else {
#pragma unroll
                    for (int q = 0; q < 6; q++) {
                        unsigned om = W[q];
                        int D0 = 223 - 32 * q + lane;
                        while (om) {
                            int b = __ffs(om) - 1; om &= om - 1u;
                            a0 += kpad[(D0 - b) * KSTR + wid];
                            if (om) {
                                b = __ffs(om) - 1; om &= om - 1u;
                                a1 += kpad[(D0 - b) * KSTR + wid];
                            }
                        }
                    }
                    return a0 + a1;
                }
            };

            float Pp = Pn_sh[c & 1][i * KSTR + s];
            float bP = basev + Pp + powt[i] * MB0[s] + wt[i] * MA0[s];
            float acc = 0.f;
            // ---- prev-chunk applies (k-only; MB0 carries the inj history) ----
            {
                const unsigned* balwP = balw[(c & 1) ^ 1];
#pragma unroll 4
                for (int r = 0; r < 16; r++) {
                    unsigned bw = balwP[r];
                    int dA = i + 31 - 2 * r;
                    acc += (((bw >> s) & 1u) ? kpad[dA * KSTR + s] : 0.f)
                         + (((bw >> (16 + s)) & 1u) ? kpad[(dA - 1) * KSTR + s] : 0.f);
                }
            }
            bool doPn = (c + 1 < NCHUNK);
            float Pv = 0.f;
            if (wid >= 8 && doPn) Pv = computePn();   // hidden in pre-wait idle

            // ---- wavefront ----
            unsigned* balwC = balw[c & 1];
            if (wid > 0) {
                PAIR_BAR(wid);
                for (int r = 0; r < wid; r++) {
                    unsigned bw = balwC[r];
                    int dA = i - 1 - 2 * r;
                    acc += (((bw >> s) & 1u) ? kpad[dA * KSTR + s] : 0.f)
                         + (((bw >> (16 + s)) & 1u) ? kpad[(dA - 1) * KSTR + s] : 0.f)
                         + wt[dA] * inj_sh[(2 * r) * SUB + s]
                         + wt[dA - 1] * inj_sh[(2 * r + 1) * SUB + s];
                }
            } else if (lane < 16) {
                ring[((t0 >> 5) & 15) * SUB + lane] = 0u;
            }
            float subA = bP + acc;
            bool pa = (lane < 16) && (subA > 0.f);
            unsigned balA = __ballot_sync(0xFFFFFFFFu, pa) & 0xFFFFu;
            float subB = subA + (((balA >> s) & 1u) ? k0reg : 0.f);
            bool pbv = (lane >= 16) && (subB > 0.f);
            unsigned balB = __ballot_sync(0xFFFFFFFFu, pbv) >> 16;
            unsigned mybal = (lane < 16) ? balA : balB;
            float inj = lut[0][mybal & 15][s] + lut[1][(mybal >> 4) & 15][s]
                      + lut[2][(mybal >> 8) & 15][s] + lut[3][(mybal >> 12) & 15][s];
            inj_sh[i * SUB + s] = inj;
            if (lane == 0) balwC[wid] = balA | (balB << 16);
            float injB = __shfl_sync(0xFFFFFFFFu, inj, (lane & 15) + 16);
            float myA = 0.f, myB = 0.f;
            if (lane < 16) {
                myA = powt[31 - 2 * wid] * inj + powt[30 - 2 * wid] * injB;
                myB = wt[31 - 2 * wid] * inj + wt[30 - 2 * wid] * injB;
                if (wid < 15) { sApart[wid * SUB + s] = myA; sBpart[wid * SUB + s] = myB; }
                unsigned bits = (((balA >> s) & 1u) << (2 * wid)) | (((balB >> s) & 1u) << (2 * wid + 1));
                atomicOr(&ring[((t0 >> 5) & 15) * SUB + s], bits);
            }
            if (wid < 15) PAIR_BAR(wid + 1);

            // ---- off-critical-path ----
            spk_out[(t0 + i) * SUB + s] = ((mybal >> s) & 1u) ? 1.f : 0.f;
            float nextbase = 0.f;
            if (c + 1 < NCHUNK) nextbase = g_base[(t0 + CHUNK + i) * SUB + s];
            if (wid == 15 && lane < 16) {
                float sA = myA, sB = myB;
                for (int r = 0; r < 15; r++) {
                    sA += sApart[r * SUB + lane];
                    sB += sBpart[r * SUB + lane];
                }
                float p32 = powt[CHUNK];
                float nMA = p32 * MA0[lane] + sA;
                float nMB = p32 * MB0[lane] + 32.f * p32 * MA0[lane] + sB;
                MA0[lane] = nMA;
                MB0[lane] = nMB;
            }
            if (wid < 8 && doPn) Pv = computePn();    // hidden in post-release idle
            if (doPn) Pn_sh[(c + 1) & 1][lane * KSTR + wid] = Pv;
            __syncthreads();
            basev = nextbase;
        } else {
            // ---- general fallback: per-thread pre-phase + serial loop (non-uniform rho) ----
            float P = 0.f;
            {
                int t = t0 + i;
                int uhi = t0 - 1;
                int ulo = t - TNO; if (ulo < 0) ulo = 0;
                if (uhi >= ulo) {
                    int wlo = ulo >> 5;
#pragma unroll
                    for (int q8 = 0; q8 < 8; q8++) {
                        int w = wlo + q8;
                        int bu = w << 5;
                        unsigned valid = 0u;
                        if (bu >= 0 && bu <= uhi) {
                            valid = 0xFFFFFFFFu;
                            if (bu < ulo) valid <<= (ulo - bu);
                            int hb = uhi - bu;
                            if (hb < 31) valid &= ((2u << hb) - 1u);
                        }
                        unsigned om = (valid ? ring[(w & 15) * SUB + s] : 0u) & valid;
                        int Cw = t - 1 - (w << 5);
                        while (om) {
                            int b = __ffs(om) - 1; om &= om - 1u;
                            P += kpad[(Cw - b) * KSTR + s];
                        }
                    }
                }
            }
            P_sh[tid] = P;
            base_sh[tid] = basev;
            __syncthreads();
            if (tid < 16) {
                int ss = tid;
                unsigned myhist = 0u;
                float rho_s = rho_sh[ss];
                for (int ii = 0; ii < CHUNK; ii++) {
                    float Pv2 = P_sh[ii * SUB + ss];
                    float bv = base_sh[ii * SUB + ss];
                    unsigned m = ii ? ((1u << ii) - 1u) : 0u;
                    unsigned om = myhist & m;
                    float intra;
                    if (2 * __popc(om) > ii) {
                        unsigned zm = om ^ m;
                        float a = 0.f;
                        while (zm) { int b = __ffs(zm) - 1; zm &= zm - 1u; a += kpad[b * KSTR + ss]; }
                        intra = Kpre_sh[ii * KSTR + ss] - a;
                    } else {
                        float a = 0.f;
                        while (om) { int b = __ffs(om) - 1; om &= om - 1u; a += kpad[b * KSTR + ss]; }
                        intra = a;
                    }
                    float sub = bv + Pv2 + intra + MBr;
                    bool sp = sub > 0.f;
                    spf[ii * SUB + ss] = sp ? 1.f : 0.f;
                    myhist = (myhist << 1) | (sp ? 1u : 0u);
                    float Ao = A;
                    B = rho_s * (B + Ao);
                    A = rho_s * Ao + (sp ? 1.f : 0.f);
                    float accv = 0.f;
#pragma unroll
                    for (int q = 0; q < 16; q++)
                        accv += cwrow[q] * __shfl_sync(0x0000FFFFu, B, q);
                    MBr = accv;
                }
                ring[((t0 >> 5) & 15) * SUB + ss] = __brev(myhist);
            }
            __syncthreads();
            spk_out[t0 * SUB + tid] = spf[tid];
            float nextbase = 0.f;
            if (c + 1 < NCHUNK) nextbase = g_base[(t0 + CHUNK + i) * SUB + s];
            __syncthreads();
            basev = nextbase;
        }
    }
}

// ---------------- launch ----------------
extern "C" void kernel_launch(void* const* d_in, const int* in_sizes, int n_in,
                              void* d_out, int out_size)
{
    const float* S_e     = (const float*)d_in[0];
    const float* S_i     = (const float*)d_in[1];
    const float* C_den   = (const float*)d_in[2];
    const float* C_syn_e = (const float*)d_in[3];
    const float* C_syn_i = (const float*)d_in[4];
    const float* Tau_e   = (const float*)d_in[5];
    const float* Tau_i   = (const float*)d_in[6];
    const float* W_e     = (const float*)d_in[7];
    const float* W_i     = (const float*)d_in[8];
    const float* D_e     = (const float*)d_in[9];
    const float* D_i     = (const float*)d_in[10];
    const float* Tau_spk = (const float*)d_in[11];
    const float* W_spk   = (const float*)d_in[12];
    const float* W_hist  = (const float*)d_in[13];
    const float* Theta   = (const float*)d_in[14];
    float* out = (float*)d_out;
    float* out_filters = out + T_DATA * SUB;

    k_setup<<<1, 256>>>(C_den, C_syn_e, C_syn_i, Tau_e, Tau_i, W_e, W_i,
                        D_e, D_i, Tau_spk, W_spk, W_hist, out_filters);
    k_segsum<<<T_DATA / SEG_ROWS, 256>>>(S_e, S_i);
    k_conv<<<(T_DATA + TILE_T - 1) / TILE_T, 256>>>(Theta);
    k_scan<<<1, 512>>>(out);
}

// round 10
// speedup vs baseline: 3.0380x; 1.4523x over previous
#include <cuda_runtime.h>
#include <math.h>

#define T_DATA 20000
#define SUB 16
#define TNO 200
#define ENO 2000
#define INO 500
#define CHUNK 32
#define NCHUNK (T_DATA / CHUNK)
#define KSTR 17
#define PI_F 3.14159265358979323846f

// ---------------- device scratch (no allocs allowed) ----------------
__device__ float g_syn_e[T_DATA * SUB];
__device__ float g_syn_i[T_DATA * SUB];
__device__ float g_base[T_DATA * SUB];
__device__ float g_ekT[TNO * SUB];   // [j][s]
__device__ float g_ikT[TNO * SUB];   // [j][s]
__device__ float g_hkT[TNO * SUB];   // [j][s] hist kernel
__device__ unsigned char g_seg_e[ENO];
__device__ unsigned char g_seg_i[INO];
__device__ float g_cw[SUB * SUB];
__device__ float g_rho[SUB];
__device__ int   g_fast;

#define PAIR_BAR(id) asm volatile("bar.sync %0, %1;" :: "r"(id), "r"(64) : "memory")

// ---------------- K0: setup ----------------
__global__ void k_setup(const float* C_den, const float* C_syn_e, const float* C_syn_i,
                        const float* Tau_e, const float* Tau_i,
                        const float* W_e, const float* W_i,
                        const float* D_e, const float* D_i,
                        const float* Tau_spk, const float* W_spk,
                        const float* W_hist, float* out_filters)
{
    int tid = threadIdx.x;
    for (int idx = tid; idx < SUB * TNO; idx += blockDim.x) {
        int s = idx / TNO, j = idx % TNO;
        float t = (float)j;
        float te  = fmaxf(t - expf(D_e[s]), 0.f);
        float tte = te / expf(Tau_e[s]);
        float ek  = tte * expf(-tte) * expf(W_e[s]);
        float ti  = fmaxf(t - expf(D_i[s]), 0.f);
        float tti = ti / expf(Tau_i[s]);
        float ik  = -tti * expf(-tti) * expf(W_i[s]);
        float tts = t / expf(Tau_spk[s]);
        float sk  = tts * expf(-tts) * expf(W_spk[s]);
        float raw = 4.0f * logf(t + 1.0f);
        float hk = 0.f;
        for (int b = 0; b < 16; b++) {
            float phi = PI_F * 0.5f * (float)b;
            float v = 0.f;
            if (!(raw < phi - PI_F || raw > phi + PI_F))
                v = 0.5f * cosf(raw - phi) + 0.5f;
            hk += W_hist[s * 16 + b] * v;
        }
        g_ekT[j * SUB + s] = ek;
        g_ikT[j * SUB + s] = ik;
        g_hkT[j * SUB + s] = hk;
        out_filters[(0  + s) * TNO + j] = ek;
        out_filters[(16 + s) * TNO + j] = ik;
        out_filters[(32 + s) * TNO + j] = sk;
        out_filters[(48 + s) * TNO + j] = hk;
    }
    for (int e = tid; e < ENO; e += blockDim.x) {
        int seg = 0;
        for (int s = 0; s < SUB; s++) if (C_syn_e[s * ENO + e] > 0.5f) seg = s;
        g_seg_e[e] = (unsigned char)seg;
    }
    for (int e = tid; e < INO; e += blockDim.x) {
        int seg = 0;
        for (int s = 0; s < SUB; s++) if (C_syn_i[s * INO + e] > 0.5f) seg = s;
        g_seg_i[e] = (unsigned char)seg;
    }
    if (tid < SUB) g_rho[tid] = expf(-1.0f / expf(Tau_spk[tid]));
    if (tid < SUB * SUB) {
        int s = tid >> 4, q = tid & 15;
        g_cw[s * SUB + q] = C_den[s * SUB + q] * expf(W_spk[q]) / expf(Tau_spk[q]);
    }
    __syncthreads();
    if (tid == 0) {
        int fast = 1;
        float r0 = g_rho[0];
        for (int s = 1; s < SUB; s++) if (g_rho[s] != r0) fast = 0;
        g_fast = fast;
    }
}

// ---------------- K1: segment sums ----------------
#define SEG_ROWS 4
__global__ void k_segsum(const float* __restrict__ S_e, const float* __restrict__ S_i)
{
    __shared__ unsigned char sege[ENO];
    __shared__ unsigned char segi[INO];
    __shared__ float acc[SEG_ROWS][32];
    int tid = threadIdx.x;
    for (int e = tid; e < ENO; e += blockDim.x) sege[e] = g_seg_e[e];
    for (int e = tid; e < INO; e += blockDim.x) segi[e] = g_seg_i[e];
    if (tid < SEG_ROWS * 32) ((float*)acc)[tid] = 0.f;
    __syncthreads();
    int t0 = blockIdx.x * SEG_ROWS;
    for (int r = 0; r < SEG_ROWS; r++) {
        const float* re = S_e + (size_t)(t0 + r) * ENO;
        for (int e = tid; e < ENO; e += blockDim.x) {
            float v = re[e];
            if (v != 0.f) atomicAdd(&acc[r][sege[e]], v);
        }
        const float* ri = S_i + (size_t)(t0 + r) * INO;
        for (int e = tid; e < INO; e += blockDim.x) {
            float v = ri[e];
            if (v != 0.f) atomicAdd(&acc[r][16 + segi[e]], v);
        }
    }
    __syncthreads();
    if (tid < SEG_ROWS * 32) {
        int r = tid >> 5, q = tid & 31;
        if (q < 16) g_syn_e[(t0 + r) * SUB + q] = acc[r][q];
        else        g_syn_i[(t0 + r) * SUB + (q - 16)] = acc[r][q];
    }
}

// ---------------- K2: causal depthwise FIR + Theta -> base ----------------
#define TILE_T 128
__global__ void k_conv(const float* __restrict__ Theta)
{
    __shared__ float se[(TILE_T + TNO) * SUB];
    __shared__ float si[(TILE_T + TNO) * SUB];
    int t0 = blockIdx.x * TILE_T;
    int tid = threadIdx.x;
    for (int idx = tid; idx < 327 * SUB; idx += blockDim.x) {
        int r = idx / SUB, s = idx % SUB;
        int tt = t0 - 200 + r;
        float ve = 0.f, vi = 0.f;
        if (tt >= 0 && tt < T_DATA) {
            ve = g_syn_e[tt * SUB + s];
            vi = g_syn_i[tt * SUB + s];
        }
        se[idx] = ve;
        si[idx] = vi;
    }
    __syncthreads();
    int s = tid & 15, tg = tid >> 4;
    float th = Theta[s];
    float acc[8];
#pragma unroll
    for (int k = 0; k < 8; k++) acc[k] = th;
    for (int j = 0; j < TNO; j++) {
        float ke = g_ekT[j * SUB + s];
        float ki = g_ikT[j * SUB + s];
#pragma unroll
        for (int k = 0; k < 8; k++) {
            int tl = tg + k * 16;
            int row = tl + 199 - j;
            acc[k] += ke * se[row * SUB + s] + ki * si[row * SUB + s];
        }
    }
#pragma unroll
    for (int k = 0; k < 8; k++) {
        int t = t0 + tg + k * 16;
        if (t < T_DATA) g_base[t * SUB + s] = acc[k];
    }
}

// ---------------- K3: 8-warp 4-step wavefront + 8 Pn warps ----------------
__global__ void __launch_bounds__(512, 1) k_scan(float* __restrict__ spk_out)
{
    __shared__ float kpad[256 * KSTR];
    __shared__ unsigned ring[16 * SUB];
    __shared__ float inj_sh[CHUNK * SUB];
    __shared__ unsigned balw1[2][8], balw2[2][8];   // double-buffered ballots (phase1, phase2)
    __shared__ float lut[4][16][16];
    __shared__ float S2_sh[32 * KSTR];
    __shared__ float Pn_sh[2][32 * KSTR];
    __shared__ float cw_sh[SUB * 17];
    __shared__ float rho_sh[SUB];
    __shared__ float MA0[SUB], MB0[SUB];
    __shared__ float powt[CHUNK + 1], wt[CHUNK + 1];
    __shared__ int fast_sh;
    // fallback-only
    __shared__ float spf[CHUNK * SUB], P_sh[CHUNK * SUB], base_sh[CHUNK * SUB];
    __shared__ float Kpre_sh[32 * KSTR];

    int tid = threadIdx.x;
    int wid = tid >> 5, lane = tid & 31;

    for (int idx = tid; idx < 256 * KSTR; idx += 512) kpad[idx] = 0.f;
    for (int idx = tid; idx < 2 * 32 * KSTR; idx += 512) ((float*)Pn_sh)[idx] = 0.f;
    if (tid < 32) { ((unsigned*)balw1)[tid & 15] = 0u; ((unsigned*)balw2)[tid & 15] = 0u; }
    if (tid < 16) { ((unsigned*)balw1)[tid] = 0u; }
    if (tid >= 16 && tid < 32) { ((unsigned*)balw2)[tid - 16] = 0u; }
    if (tid < 256) {
        int s = tid >> 4, q = tid & 15;
        cw_sh[s * 17 + q] = g_cw[s * SUB + q];
        ring[tid] = 0u;
    }
    if (tid < SUB) {
        rho_sh[tid] = g_rho[tid];
        MA0[tid] = 0.f; MB0[tid] = 0.f;
    }
    if (tid == 0) fast_sh = g_fast;
    __syncthreads();
    for (int idx = tid; idx < TNO * SUB; idx += 512) {
        int j = idx >> 4, s = idx & 15;
        kpad[j * KSTR + s] = g_hkT[idx];
    }
    if (tid <= CHUNK) {
        float p = powf(rho_sh[0], (float)tid);
        powt[tid] = p;
        wt[tid] = (float)tid * p;
    }
    for (int idx = tid; idx < 1024; idx += 512) {
        int n = idx >> 8, m = (idx >> 4) & 15, ss = idx & 15;
        float v = 0.f;
        for (int b = 0; b < 4; b++)
            if ((m >> b) & 1) v += cw_sh[ss * 17 + 4 * n + b];
        lut[n][m][ss] = v;
    }
    __syncthreads();
    {
        int ii = tid >> 4, ss = tid & 15;
        float suf = 0.f;
        for (int b = ii + 32; b < TNO; b++) suf += kpad[b * KSTR + ss];
        S2_sh[ii * KSTR + ss] = suf;
        float pre = 0.f;
        for (int b = 0; b < ii; b++) pre += kpad[b * KSTR + ss];
        Kpre_sh[ii * KSTR + ss] = pre;
    }
    __syncthreads();

    // fallback state
    float MBr = 0.f, A = 0.f, B = 0.f;
    float cwrow[16];
    if (tid < 16) {
#pragma unroll
        for (int q = 0; q < 16; q++) cwrow[q] = cw_sh[tid * 17 + q];
    }
    const int fi = tid >> 4, fs = tid & 15;
    float fbase = g_base[fi * SUB + fs];

    // chain-lane constants
    const int half = lane >> 4, sc = lane & 15;
    const int i1 = 4 * wid + half, i2 = i1 + 2;       // valid for wid<8
    float k0c = kpad[sc], k1c = kpad[KSTR + sc], k2c = kpad[2 * KSTR + sc];
    float wt1s = wt[1], wt2s = wt[2], p32 = powt[CHUNK];
    float powi1 = 0.f, wti1 = 0.f, powi2 = 0.f, wti2 = 0.f;
    float base1 = 0.f, base2 = 0.f;
    if (wid < 8) {
        powi1 = powt[i1]; wti1 = wt[i1];
        powi2 = powt[i2]; wti2 = wt[i2];
        base1 = g_base[i1 * SUB + sc];
        base2 = g_base[i2 * SUB + sc];
    }
    const int pns0 = (wid - 8) * 2, pns1 = pns0 + 1;  // Pn warps: subunits

    for (int c = 0; c < NCHUNK; c++) {
        int t0 = c * CHUNK;

        if (fast_sh) {
            if (wid < 8) {
                // ---- prologue ----
                float bP1 = base1 + Pn_sh[c & 1][i1 * KSTR + sc] + powi1 * MB0[sc] + wti1 * MA0[sc];
                float bP2 = base2 + Pn_sh[c & 1][i2 * KSTR + sc] + powi2 * MB0[sc] + wti2 * MA0[sc];
                float acc1 = 0.f, acc2 = 0.f;
                // prev-chunk k-only applies (inj history carried by MB0)
                {
                    const unsigned* bp1 = balw1[(c & 1) ^ 1];
                    const unsigned* bp2 = balw2[(c & 1) ^ 1];
#pragma unroll
                    for (int r = 0; r < 8; r++) {
                        unsigned w1 = bp1[r], w2 = bp2[r];
                        int d = i1 + 31 - 4 * r;
                        acc1 += (((w1 >> sc) & 1u) ? kpad[d * KSTR + sc] : 0.f)
                              + (((w1 >> (16 + sc)) & 1u) ? kpad[(d - 1) * KSTR + sc] : 0.f)
                              + (((w2 >> sc) & 1u) ? kpad[(d - 2) * KSTR + sc] : 0.f)
                              + (((w2 >> (16 + sc)) & 1u) ? kpad[(d - 3) * KSTR + sc] : 0.f);
                        int e = d + 2;
                        acc2 += (((w1 >> sc) & 1u) ? kpad[e * KSTR + sc] : 0.f)
                              + (((w1 >> (16 + sc)) & 1u) ? kpad[(e - 1) * KSTR + sc] : 0.f)
                              + (((w2 >> sc) & 1u) ? kpad[(e - 2) * KSTR + sc] : 0.f)
                              + (((w2 >> (16 + sc)) & 1u) ? kpad[(e - 3) * KSTR + sc] : 0.f);
                    }
                }
                if (wid == 0) {
                    if (half == 0) ring[(c & 15) * SUB + sc] = 0u;
                } else {
                    PAIR_BAR(wid);
                    const unsigned* bc1 = balw1[c & 1];
                    const unsigned* bc2 = balw2[c & 1];
                    for (int r = 0; r < wid; r++) {
                        unsigned w1 = bc1[r], w2 = bc2[r];
                        int u0 = 4 * r;
                        int d = i1 - 1 - u0;
                        acc1 += (((w1 >> sc) & 1u) ? kpad[d * KSTR + sc] : 0.f)
                              + (((w1 >> (16 + sc)) & 1u) ? kpad[(d - 1) * KSTR + sc] : 0.f)
                              + (((w2 >> sc) & 1u) ? kpad[(d - 2) * KSTR + sc] : 0.f)
                              + (((w2 >> (16 + sc)) & 1u) ? kpad[(d - 3) * KSTR + sc] : 0.f)
                              + wt[d] * inj_sh[u0 * SUB + sc]
                              + wt[d - 1] * inj_sh[(u0 + 1) * SUB + sc]
                              + wt[d - 2] * inj_sh[(u0 + 2) * SUB + sc]
                              + wt[d - 3] * inj_sh[(u0 + 3) * SUB + sc];
                        int e = d + 2;
                        acc2 += (((w1 >> sc) & 1u) ? kpad[e * KSTR + sc] : 0.f)
                              + (((w1 >> (16 + sc)) & 1u) ? kpad[(e - 1) * KSTR + sc] : 0.f)
                              + (((w2 >> sc) & 1u) ? kpad[(e - 2) * KSTR + sc] : 0.f)
                              + (((w2 >> (16 + sc)) & 1u) ? kpad[(e - 3) * KSTR + sc] : 0.f)
                              + wt[e] * inj_sh[u0 * SUB + sc]
                              + wt[e - 1] * inj_sh[(u0 + 1) * SUB + sc]
                              + wt[e - 2] * inj_sh[(u0 + 2) * SUB + sc]
                              + wt[e - 3] * inj_sh[(u0 + 3) * SUB + sc];
                    }
                }
                // ---- phase 1: steps 4w, 4w+1 ----
                float sub1 = bP1 + acc1;
                bool pA = (half == 0) && (sub1 > 0.f);
                unsigned balA = __ballot_sync(0xFFFFFFFFu, pA) & 0xFFFFu;
                float sub1b = sub1 + (((balA >> sc) & 1u) ? k0c : 0.f);
                bool pB = (half == 1) && (sub1b > 0.f);
                unsigned balB = __ballot_sync(0xFFFFFFFFu, pB) >> 16;
                unsigned myb1 = half ? balB : balA;
                float injE1 = lut[0][myb1 & 15][sc] + lut[1][(myb1 >> 4) & 15][sc]
                            + lut[2][(myb1 >> 8) & 15][sc] + lut[3][(myb1 >> 12) & 15][sc];
                float inj0s = __shfl_sync(0xFFFFFFFFu, injE1, sc);
                float inj1s = __shfl_sync(0xFFFFFFFFu, injE1, sc + 16);
                unsigned spk0 = (balA >> sc) & 1u, spk1 = (balB >> sc) & 1u;
                // ---- phase 2: steps 4w+2, 4w+3 ----
                float sub2 = bP2 + acc2
                    + (spk0 ? (half ? k2c : k1c) : 0.f)
                    + (half ? wt2s : wt1s) * inj0s
                    + (spk1 ? (half ? k1c : k0c) : 0.f)
                    + (half ? wt1s * inj1s : 0.f);
                bool pC = (half == 0) && (sub2 > 0.f);
                unsigned balC = __ballot_sync(0xFFFFFFFFu, pC) & 0xFFFFu;
                float sub2b = sub2 + (((balC >> sc) & 1u) ? k0c : 0.f);
                bool pD = (half == 1) && (sub2b > 0.f);
                unsigned balD = __ballot_sync(0xFFFFFFFFu, pD) >> 16;
                unsigned myb2 = half ? balD : balC;
                float injE2 = lut[0][myb2 & 15][sc] + lut[1][(myb2 >> 4) & 15][sc]
                            + lut[2][(myb2 >> 8) & 15][sc] + lut[3][(myb2 >> 12) & 15][sc];
                // ---- publish (minimal) + release ----
                inj_sh[i1 * SUB + sc] = injE1;
                inj_sh[i2 * SUB + sc] = injE2;
                if (lane == 0) {
                    balw1[c & 1][wid] = balA | (balB << 16);
                    balw2[c & 1][wid] = balC | (balD << 16);
                }
                if (wid < 7) PAIR_BAR(wid + 1);
                // ---- post-release ----
                if (half == 0) {
                    unsigned spk2 = (balC >> sc) & 1u, spk3 = (balD >> sc) & 1u;
                    unsigned bits = (spk0 << (4 * wid)) | (spk1 << (4 * wid + 1))
                                  | (spk2 << (4 * wid + 2)) | (spk3 << (4 * wid + 3));
                    atomicOr(&ring[(c & 15) * SUB + sc], bits);
                }
                spk_out[(t0 + i1) * SUB + sc] = ((myb1 >> sc) & 1u) ? 1.f : 0.f;
                spk_out[(t0 + i2) * SUB + sc] = ((myb2 >> sc) & 1u) ? 1.f : 0.f;
                if (c + 1 < NCHUNK) {
                    base1 = g_base[(t0 + CHUNK + i1) * SUB + sc];
                    base2 = g_base[(t0 + CHUNK + i2) * SUB + sc];
                }
                if (wid == 7) {
                    // chain tail: closed-form MA/MB update from inj history
                    float sAp = 0.f, sBp = 0.f;
                    int u0 = half * 14;
                    for (int u = u0; u < u0 + 14; u++) {
                        float v = inj_sh[u * SUB + sc];
                        sAp += powt[31 - u] * v;
                        sBp += wt[31 - u] * v;
                    }
                    sAp += powt[31 - i1] * injE1 + powt[31 - i2] * injE2;
                    sBp += wt[31 - i1] * injE1 + wt[31 - i2] * injE2;
                    float sA = sAp + __shfl_xor_sync(0xFFFFFFFFu, sAp, 16);
                    float sB = sBp + __shfl_xor_sync(0xFFFFFFFFu, sBp, 16);
                    if (half == 0) {
                        float nMA = p32 * MA0[sc] + sA;
                        float nMB = p32 * MB0[sc] + 32.f * p32 * MA0[sc] + sB;
                        MA0[sc] = nMA;
                        MB0[sc] = nMB;
                    }
                }
            } else {
                // ---- Pn warps: next-chunk pre-history, 2 subunits each ----
                if (c + 1 < NCHUNK) {
                    int wbase = c - 6;
#pragma unroll
                    for (int pass = 0; pass < 2; pass++) {
                        int s = pass ? pns1 : pns0;
                        unsigned W[6];
                        int ones = 0;
#pragma unroll
                        for (int q = 0; q < 6; q++) {
                            int w = wbase + q;
                            unsigned wd = (w >= 0) ? ring[(w & 15) * SUB + s] : 0u;
                            W[q] = wd;
                            ones += __popc(wd);
                        }
                        float a0 = 0.f, a1 = 0.f;
                        float Pv;
                        if (2 * ones > 192) {
#pragma unroll
                            for (int q = 0; q < 6; q++) {
                                unsigned zm = ~W[q];
                                int D0 = 223 - 32 * q + lane;
                                while (zm) {
                                    int b = __ffs(zm) - 1; zm &= zm - 1u;
                                    a0 += kpad[(D0 - b) * KSTR + s];
                                    if (zm) {
                                        b = __ffs(zm) - 1; zm &= zm - 1u;
                                        a1 += kpad[(D0 - b) * KSTR + s];
                                    }
                                }
                            }
                            Pv = S2_sh[lane * KSTR + s] - a0 - a1;
                        } else {
#pragma unroll
                            for (int q = 0; q < 6; q++) {
                                unsigned om = W[q];
                                int D0 = 223 - 32 * q + lane;
                                while (om) {
                                    int b = __ffs(om) - 1; om &= om - 1u;
                                    a0 += kpad[(D0 - b) * KSTR + s];
                                    if (om) {
                                        b = __ffs(om) - 1; om &= om - 1u;
                                        a1 += kpad[(D0 - b) * KSTR + s];
                                    }
                                }
                            }
                            Pv = a0 + a1;
                        }
                        Pn_sh[(c + 1) & 1][lane * KSTR + s] = Pv;
                    }
                }
            }
            __syncthreads();
        } else {
            // ---- general fallback: per-thread pre-phase + serial loop ----
            float P = 0.f;
            {
                int t = t0 + fi;
                int uhi = t0 - 1;
                int ulo = t - TNO; if (ulo < 0) ulo = 0;
                if (uhi >= ulo) {
                    int wlo = ulo >> 5;
#pragma unroll
                    for (int q8 = 0; q8 < 8; q8++) {
                        int w = wlo + q8;
                        int bu = w << 5;
                        unsigned valid = 0u;
                        if (bu >= 0 && bu <= uhi) {
                            valid = 0xFFFFFFFFu;
                            if (bu < ulo) valid <<= (ulo - bu);
                            int hb = uhi - bu;
                            if (hb < 31) valid &= ((2u << hb) - 1u);
                        }
                        unsigned om = (valid ? ring[(w & 15) * SUB + fs] : 0u) & valid;
                        int Cw = t - 1 - (w << 5);
                        while (om) {
                            int b = __ffs(om) - 1; om &= om - 1u;
                            P += kpad[(Cw - b) * KSTR + fs];
                        }
                    }
                }
            }
            P_sh[tid] = P;
            base_sh[tid] = fbase;
            __syncthreads();
            if (tid < 16) {
                int ss = tid;
                unsigned myhist = 0u;
                float rho_s = rho_sh[ss];
                for (int ii = 0; ii < CHUNK; ii++) {
                    float Pv2 = P_sh[ii * SUB + ss];
                    float bv = base_sh[ii * SUB + ss];
                    unsigned m = ii ? ((1u << ii) - 1u) : 0u;
                    unsigned om = myhist & m;
                    float intra;
                    if (2 * __popc(om) > ii) {
                        unsigned zm = om ^ m;
                        float a = 0.f;
                        while (zm) { int b = __ffs(zm) - 1; zm &= zm - 1u; a += kpad[b * KSTR + ss]; }
                        intra = Kpre_sh[ii * KSTR + ss] - a;
                    } else {
                        float a = 0.f;
                        while (om) { int b = __ffs(om) - 1; om &= om - 1u; a += kpad[b * KSTR + ss]; }
                        intra = a;
                    }
                    float sub = bv + Pv2 + intra + MBr;
                    bool sp = sub > 0.f;
                    spf[ii * SUB + ss] = sp ? 1.f : 0.f;
                    myhist = (myhist << 1) | (sp ? 1u : 0u);
                    float Ao = A;
                    B = rho_s * (B + Ao);
                    A = rho_s * Ao + (sp ? 1.f : 0.f);
                    float accv = 0.f;
#pragma unroll
                    for (int q = 0; q < 16; q++)
                        accv += cwrow[q] * __shfl_sync(0x0000FFFFu, B, q);
                    MBr = accv;
                }
                ring[((t0 >> 5) & 15) * SUB + ss] = __brev(myhist);
            }
            __syncthreads();
            spk_out[t0 * SUB + tid] = spf[tid];
            float nextbase = 0.f;
            if (c + 1 < NCHUNK) nextbase = g_base[(t0 + CHUNK + fi) * SUB + fs];
            __syncthreads();
            fbase = nextbase;
        }
    }
}

// ---------------- launch ----------------
extern "C" void kernel_launch(void* const* d_in, const int* in_sizes, int n_in,
                              void* d_out, int out_size)
{
    const float* S_e     = (const float*)d_in[0];
    const float* S_i     = (const float*)d_in[1];
    const float* C_den   = (const float*)d_in[2];
    const float* C_syn_e = (const float*)d_in[3];
    const float* C_syn_i = (const float*)d_in[4];
    const float* Tau_e   = (const float*)d_in[5];
    const float* Tau_i   = (const float*)d_in[6];
    const float* W_e     = (const float*)d_in[7];
    const float* W_i     = (const float*)d_in[8];
    const float* D_e     = (const float*)d_in[9];
    const float* D_i     = (const float*)d_in[10];
    const float* Tau_spk = (const float*)d_in[11];
    const float* W_spk   = (const float*)d_in[12];
    const float* W_hist  = (const float*)d_in[13];
    const float* Theta   = (const float*)d_in[14];
    float* out = (float*)d_out;
    float* out_filters = out + T_DATA * SUB;

    k_setup<<<1, 256>>>(C_den, C_syn_e, C_syn_i, Tau_e, Tau_i, W_e, W_i,
                        D_e, D_i, Tau_spk, W_spk, W_hist, out_filters);
    k_segsum<<<T_DATA / SEG_ROWS, 256>>>(S_e, S_i);
    k_conv<<<(T_DATA + TILE_T - 1) / TILE_T, 256>>>(Theta);
    k_scan<<<1, 512>>>(out);
}

// round 11
// speedup vs baseline: 3.0751x; 1.0122x over previous
#include <cuda_runtime.h>
#include <math.h>

#define T_DATA 20000
#define SUB 16
#define TNO 200
#define ENO 2000
#define INO 500
#define CHUNK 32
#define NCHUNK (T_DATA / CHUNK)
#define KSTR 17
#define PI_F 3.14159265358979323846f

// ---------------- device scratch (no allocs allowed) ----------------
__device__ float g_syn_e[T_DATA * SUB];
__device__ float g_syn_i[T_DATA * SUB];
__device__ float g_base[T_DATA * SUB];
__device__ float g_ekT[TNO * SUB];
__device__ float g_ikT[TNO * SUB];
__device__ float g_hkT[TNO * SUB];
__device__ unsigned char g_seg_e[ENO];
__device__ unsigned char g_seg_i[INO];
__device__ float g_cw[SUB * SUB];
__device__ float g_rho[SUB];
__device__ int   g_fast;

#define PAIR_BAR(id) asm volatile("bar.sync %0, %1;" :: "r"(id), "r"(64) : "memory")

// ---------------- K0: setup ----------------
__global__ void k_setup(const float* C_den, const float* C_syn_e, const float* C_syn_i,
                        const float* Tau_e, const float* Tau_i,
                        const float* W_e, const float* W_i,
                        const float* D_e, const float* D_i,
                        const float* Tau_spk, const float* W_spk,
                        const float* W_hist, float* out_filters)
{
    int tid = threadIdx.x;
    for (int idx = tid; idx < SUB * TNO; idx += blockDim.x) {
        int s = idx / TNO, j = idx % TNO;
        float t = (float)j;
        float te  = fmaxf(t - expf(D_e[s]), 0.f);
        float tte = te / expf(Tau_e[s]);
        float ek  = tte * expf(-tte) * expf(W_e[s]);
        float ti  = fmaxf(t - expf(D_i[s]), 0.f);
        float tti = ti / expf(Tau_i[s]);
        float ik  = -tti * expf(-tti) * expf(W_i[s]);
        float tts = t / expf(Tau_spk[s]);
        float sk  = tts * expf(-tts) * expf(W_spk[s]);
        float raw = 4.0f * logf(t + 1.0f);
        float hk = 0.f;
        for (int b = 0; b < 16; b++) {
            float phi = PI_F * 0.5f * (float)b;
            float v = 0.f;
            if (!(raw < phi - PI_F || raw > phi + PI_F))
                v = 0.5f * cosf(raw - phi) + 0.5f;
            hk += W_hist[s * 16 + b] * v;
        }
        g_ekT[j * SUB + s] = ek;
        g_ikT[j * SUB + s] = ik;
        g_hkT[j * SUB + s] = hk;
        out_filters[(0  + s) * TNO + j] = ek;
        out_filters[(16 + s) * TNO + j] = ik;
        out_filters[(32 + s) * TNO + j] = sk;
        out_filters[(48 + s) * TNO + j] = hk;
    }
    for (int e = tid; e < ENO; e += blockDim.x) {
        int seg = 0;
        for (int s = 0; s < SUB; s++) if (C_syn_e[s * ENO + e] > 0.5f) seg = s;
        g_seg_e[e] = (unsigned char)seg;
    }
    for (int e = tid; e < INO; e += blockDim.x) {
        int seg = 0;
        for (int s = 0; s < SUB; s++) if (C_syn_i[s * INO + e] > 0.5f) seg = s;
        g_seg_i[e] = (unsigned char)seg;
    }
    if (tid < SUB) g_rho[tid] = expf(-1.0f / expf(Tau_spk[tid]));
    if (tid < SUB * SUB) {
        int s = tid >> 4, q = tid & 15;
        g_cw[s * SUB + q] = C_den[s * SUB + q] * expf(W_spk[q]) / expf(Tau_spk[q]);
    }
    __syncthreads();
    if (tid == 0) {
        int fast = 1;
        float r0 = g_rho[0];
        for (int s = 1; s < SUB; s++) if (g_rho[s] != r0) fast = 0;
        g_fast = fast;
    }
}

// ---------------- K1: segment sums ----------------
#define SEG_ROWS 4
__global__ void k_segsum(const float* __restrict__ S_e, const float* __restrict__ S_i)
{
    __shared__ unsigned char sege[ENO];
    __shared__ unsigned char segi[INO];
    __shared__ float acc[SEG_ROWS][32];
    int tid = threadIdx.x;
    for (int e = tid; e < ENO; e += blockDim.x) sege[e] = g_seg_e[e];
    for (int e = tid; e < INO; e += blockDim.x) segi[e] = g_seg_i[e];
    if (tid < SEG_ROWS * 32) ((float*)acc)[tid] = 0.f;
    __syncthreads();
    int t0 = blockIdx.x * SEG_ROWS;
    for (int r = 0; r < SEG_ROWS; r++) {
        const float* re = S_e + (size_t)(t0 + r) * ENO;
        for (int e = tid; e < ENO; e += blockDim.x) {
            float v = re[e];
            if (v != 0.f) atomicAdd(&acc[r][sege[e]], v);
        }
        const float* ri = S_i + (size_t)(t0 + r) * INO;
        for (int e = tid; e < INO; e += blockDim.x) {
            float v = ri[e];
            if (v != 0.f) atomicAdd(&acc[r][16 + segi[e]], v);
        }
    }
    __syncthreads();
    if (tid < SEG_ROWS * 32) {
        int r = tid >> 5, q = tid & 31;
        if (q < 16) g_syn_e[(t0 + r) * SUB + q] = acc[r][q];
        else        g_syn_i[(t0 + r) * SUB + (q - 16)] = acc[r][q];
    }
}

// ---------------- K2: causal depthwise FIR + Theta -> base ----------------
#define TILE_T 128
__global__ void k_conv(const float* __restrict__ Theta)
{
    __shared__ float se[(TILE_T + TNO) * SUB];
    __shared__ float si[(TILE_T + TNO) * SUB];
    int t0 = blockIdx.x * TILE_T;
    int tid = threadIdx.x;
    for (int idx = tid; idx < 327 * SUB; idx += blockDim.x) {
        int r = idx / SUB, s = idx % SUB;
        int tt = t0 - 200 + r;
        float ve = 0.f, vi = 0.f;
        if (tt >= 0 && tt < T_DATA) {
            ve = g_syn_e[tt * SUB + s];
            vi = g_syn_i[tt * SUB + s];
        }
        se[idx] = ve;
        si[idx] = vi;
    }
    __syncthreads();
    int s = tid & 15, tg = tid >> 4;
    float th = Theta[s];
    float acc[8];
#pragma unroll
    for (int k = 0; k < 8; k++) acc[k] = th;
    for (int j = 0; j < TNO; j++) {
        float ke = g_ekT[j * SUB + s];
        float ki = g_ikT[j * SUB + s];
#pragma unroll
        for (int k = 0; k < 8; k++) {
            int tl = tg + k * 16;
            int row = tl + 199 - j;
            acc[k] += ke * se[row * SUB + s] + ki * si[row * SUB + s];
        }
    }
#pragma unroll
    for (int k = 0; k < 8; k++) {
        int t = t0 + tg + k * 16;
        if (t < T_DATA) g_base[t * SUB + s] = acc[k];
    }
}

// ---------------- K3: 4-warp 8-step wavefront + 8 Pn warps ----------------
__global__ void __launch_bounds__(512, 1) k_scan(float* __restrict__ spk_out)
{
    __shared__ float kpad[256 * KSTR];
    __shared__ unsigned ring[16 * SUB];
    __shared__ float inj_sh[CHUNK * SUB];
    __shared__ unsigned balw[2][4][4];      // [buf][round][phase] ballots (A | B<<16)
    __shared__ float lut[4][16][16];
    __shared__ float S2_sh[32 * KSTR];
    __shared__ float Pn_sh[2][32 * KSTR];
    __shared__ float cw_sh[SUB * 17];
    __shared__ float rho_sh[SUB];
    __shared__ float MA0[SUB], MB0[SUB];
    __shared__ float powt[CHUNK + 1], wt[CHUNK + 1];
    __shared__ int fast_sh;
    // fallback-only
    __shared__ float spf[CHUNK * SUB], P_sh[CHUNK * SUB], base_sh[CHUNK * SUB];
    __shared__ float Kpre_sh[32 * KSTR];

    int tid = threadIdx.x;
    int wid = tid >> 5, lane = tid & 31;

    for (int idx = tid; idx < 256 * KSTR; idx += 512) kpad[idx] = 0.f;
    for (int idx = tid; idx < 2 * 32 * KSTR; idx += 512) ((float*)Pn_sh)[idx] = 0.f;
    if (tid < 32) ((unsigned*)balw)[tid] = 0u;
    if (tid < 256) {
        int s = tid >> 4, q = tid & 15;
        cw_sh[s * 17 + q] = g_cw[s * SUB + q];
        ring[tid] = 0u;
    }
    if (tid < SUB) {
        rho_sh[tid] = g_rho[tid];
        MA0[tid] = 0.f; MB0[tid] = 0.f;
    }
    if (tid == 0) fast_sh = g_fast;
    __syncthreads();
    for (int idx = tid; idx < TNO * SUB; idx += 512) {
        int j = idx >> 4, s = idx & 15;
        kpad[j * KSTR + s] = g_hkT[idx];
    }
    if (tid <= CHUNK) {
        float p = powf(rho_sh[0], (float)tid);
        powt[tid] = p;
        wt[tid] = (float)tid * p;
    }
    for (int idx = tid; idx < 1024; idx += 512) {
        int n = idx >> 8, m = (idx >> 4) & 15, ss = idx & 15;
        float v = 0.f;
        for (int b = 0; b < 4; b++)
            if ((m >> b) & 1) v += cw_sh[ss * 17 + 4 * n + b];
        lut[n][m][ss] = v;
    }
    __syncthreads();
    {
        int ii = tid >> 4, ss = tid & 15;
        float suf = 0.f;
        for (int b = ii + 32; b < TNO; b++) suf += kpad[b * KSTR + ss];
        S2_sh[ii * KSTR + ss] = suf;
        float pre = 0.f;
        for (int b = 0; b < ii; b++) pre += kpad[b * KSTR + ss];
        Kpre_sh[ii * KSTR + ss] = pre;
    }
    __syncthreads();

    // fallback state
    float MBr = 0.f, A = 0.f, B = 0.f;
    float cwrow[16];
    if (tid < 16) {
#pragma unroll
        for (int q = 0; q < 16; q++) cwrow[q] = cw_sh[tid * 17 + q];
    }
    const int fi = tid >> 4, fs = tid & 15;
    float fbase = g_base[fi * SUB + fs];

    // chain constants
    const int half = lane >> 4, sc = lane & 15;
    float kcr[7], wtr[7];
#pragma unroll
    for (int d = 0; d < 7; d++) { kcr[d] = kpad[d * KSTR + sc]; wtr[d] = wt[d]; }
    float p32 = powt[CHUNK];
    float invp32 = 1.f / p32;
    float base_r[4], powi[4], wti[4], rpw[4], ipm[4];
    if (wid < 4) {
#pragma unroll
        for (int p = 0; p < 4; p++) {
            int ip = 8 * wid + 2 * p + half;
            powi[p] = powt[ip];
            wti[p] = wt[ip];
            rpw[p] = powt[ip] * invp32;
            ipm[p] = (float)(ip - 32);
            base_r[p] = g_base[ip * SUB + sc];
        }
    }
    const int pns0 = (wid - 8) * 2, pns1 = pns0 + 1;

    for (int c = 0; c < NCHUNK; c++) {
        int t0 = c * CHUNK;

        if (fast_sh) {
            if (wid < 4) {
                // ---- prologue: bP + prev-chunk k applies ----
                float mb = MB0[sc], ma = MA0[sc];
                float bPv[4], acck[4];
#pragma unroll
                for (int p = 0; p < 4; p++) {
                    int ip = 8 * wid + 2 * p + half;
                    bPv[p] = base_r[p] + Pn_sh[c & 1][ip * KSTR + sc] + powi[p] * mb + wti[p] * ma;
                    acck[p] = 0.f;
                }
                {
                    const unsigned (*bp)[4] = balw[(c & 1) ^ 1];
#pragma unroll
                    for (int r = 0; r < 4; r++) {
#pragma unroll
                        for (int ph = 0; ph < 4; ph++) {
                            unsigned bw = bp[r][ph];
                            float fe = (float)((bw >> sc) & 1u);
                            float fo = (float)((bw >> (16 + sc)) & 1u);
                            int ue = 8 * r + 2 * ph;
#pragma unroll
                            for (int p = 0; p < 4; p++) {
                                int de = (8 * wid + 2 * p + half) + 31 - ue;
                                acck[p] += fe * kpad[de * KSTR + sc] + fo * kpad[(de - 1) * KSTR + sc];
                            }
                        }
                    }
                }
                float Qa = 0.f, Qb = 0.f;
                if (wid == 0) {
                    if (half == 0) ring[(c & 15) * SUB + sc] = 0u;
                } else {
                    PAIR_BAR(wid);
                    const unsigned (*bc)[4] = balw[c & 1];
#pragma unroll
                    for (int r = 0; r < 3; r++) if (r < wid) {
#pragma unroll
                        for (int ph = 0; ph < 4; ph++) {
                            unsigned bw = bc[r][ph];
                            float fe = (float)((bw >> sc) & 1u);
                            float fo = (float)((bw >> (16 + sc)) & 1u);
                            int ue = 8 * r + 2 * ph;
                            float je = inj_sh[ue * SUB + sc];
                            float jo = inj_sh[(ue + 1) * SUB + sc];
                            Qa += powt[31 - ue] * je + powt[30 - ue] * jo;
                            Qb += wt[31 - ue] * je + wt[30 - ue] * jo;
#pragma unroll
                            for (int p = 0; p < 4; p++) {
                                int de = (8 * wid + 2 * p + half) - 1 - ue;
                                acck[p] += fe * kpad[de * KSTR + sc] + fo * kpad[(de - 1) * KSTR + sc];
                            }
                        }
                    }
                }
                // ---- 4 in-warp phases (8 steps) ----
                unsigned balAv[4], balBv[4], mybv[4];
                float injE[4];
                float inw[4] = {0.f, 0.f, 0.f, 0.f};
#pragma unroll
                for (int p = 0; p < 4; p++) {
                    float sub = bPv[p] + acck[p] + inw[p] + rpw[p] * (ipm[p] * Qa + Qb);
                    bool pa = (half == 0) && (sub > 0.f);
                    unsigned bA = __ballot_sync(0xFFFFFFFFu, pa) & 0xFFFFu;
                    float subB = sub + (((bA >> sc) & 1u) ? kcr[0] : 0.f);
                    bool pb = (half == 1) && (subB > 0.f);
                    unsigned bB = __ballot_sync(0xFFFFFFFFu, pb) >> 16;
                    balAv[p] = bA; balBv[p] = bB;
                    unsigned myb = half ? bB : bA;
                    mybv[p] = myb;
                    float ie = lut[0][myb & 15][sc] + lut[1][(myb >> 4) & 15][sc]
                             + lut[2][(myb >> 8) & 15][sc] + lut[3][(myb >> 12) & 15][sc];
                    injE[p] = ie;
                    if (p < 3) {
                        float je = __shfl_sync(0xFFFFFFFFu, ie, sc);
                        float jo = __shfl_sync(0xFFFFFFFFu, ie, sc + 16);
                        float fe = (float)((bA >> sc) & 1u);
                        float fo = (float)((bB >> sc) & 1u);
#pragma unroll
                        for (int pp = p + 1; pp < 4; pp++) {
                            const int bd = 2 * (pp - p) - 1;   // 1,3,5
                            float kA = half ? kcr[bd + 1] : kcr[bd];
                            float kB = half ? kcr[bd] : kcr[bd - 1];
                            float wA = half ? wtr[bd + 1] : wtr[bd];
                            float wB = half ? wtr[bd] : wtr[bd - 1];
                            inw[pp] += fe * kA + wA * je + fo * kB + wB * jo;
                        }
                    }
                }
                // ---- publish + release ----
#pragma unroll
                for (int p = 0; p < 4; p++)
                    inj_sh[(8 * wid + 2 * p + half) * SUB + sc] = injE[p];
                if (lane == 0) {
                    balw[c & 1][wid][0] = balAv[0] | (balBv[0] << 16);
                    balw[c & 1][wid][1] = balAv[1] | (balBv[1] << 16);
                    balw[c & 1][wid][2] = balAv[2] | (balBv[2] << 16);
                    balw[c & 1][wid][3] = balAv[3] | (balBv[3] << 16);
                }
                if (wid < 3) PAIR_BAR(wid + 1);
                // ---- post-release ----
                if (half == 0) {
                    unsigned bits = 0u;
#pragma unroll
                    for (int p = 0; p < 4; p++)
                        bits |= (((balAv[p] >> sc) & 1u) << (8 * wid + 2 * p))
                              | (((balBv[p] >> sc) & 1u) << (8 * wid + 2 * p + 1));
                    atomicOr(&ring[(c & 15) * SUB + sc], bits);
                }
#pragma unroll
                for (int p = 0; p < 4; p++)
                    spk_out[(t0 + 8 * wid + 2 * p + half) * SUB + sc] = ((mybv[p] >> sc) & 1u) ? 1.f : 0.f;
                if (c + 1 < NCHUNK) {
#pragma unroll
                    for (int p = 0; p < 4; p++)
                        base_r[p] = g_base[(t0 + CHUNK + 8 * wid + 2 * p + half) * SUB + sc];
                }
                if (wid == 3) {
                    float sAp = 0.f, sBp = 0.f;
                    int u0 = half * 12;
#pragma unroll
                    for (int u = 0; u < 12; u++) {
                        float v = inj_sh[(u0 + u) * SUB + sc];
                        sAp += powt[31 - (u0 + u)] * v;
                        sBp += wt[31 - (u0 + u)] * v;
                    }
#pragma unroll
                    for (int p = 0; p < 4; p++) {
                        int ipp = 24 + 2 * p + half;
                        sAp += powt[31 - ipp] * injE[p];
                        sBp += wt[31 - ipp] * injE[p];
                    }
                    float sA = sAp + __shfl_xor_sync(0xFFFFFFFFu, sAp, 16);
                    float sB = sBp + __shfl_xor_sync(0xFFFFFFFFu, sBp, 16);
                    if (half == 0) {
                        float nMA = p32 * MA0[sc] + sA;
                        float nMB = p32 * MB0[sc] + 32.f * p32 * MA0[sc] + sB;
                        MA0[sc] = nMA;
                        MB0[sc] = nMB;
                    }
                }
            } else if (wid >= 8) {
                // ---- Pn warps: next-chunk pre-history, 2 subunits each ----
                if (c + 1 < NCHUNK) {
                    int wbase = c - 6;
#pragma unroll
                    for (int pass = 0; pass < 2; pass++) {
                        int s = pass ? pns1 : pns0;
                        unsigned W[6];
                        int ones = 0;
#pragma unroll
                        for (int q = 0; q < 6; q++) {
                            int w = wbase + q;
                            unsigned wd = (w >= 0) ? ring[(w & 15) * SUB + s] : 0u;
                            W[q] = wd;
                            ones += __popc(wd);
                        }
                        float a0 = 0.f, a1 = 0.f;
                        float Pv;
                        if (2 * ones > 192) {
#pragma unroll
                            for (int q = 0; q < 6; q++) {
                                unsigned zm = ~W[q];
                                int D0 = 223 - 32 * q + lane;
                                while (zm) {
                                    int b = __ffs(zm) - 1; zm &= zm - 1u;
                                    a0 += kpad[(D0 - b) * KSTR + s];
                                    if (zm) {
                                        b = __ffs(zm) - 1; zm &= zm - 1u;
                                        a1 += kpad[(D0 - b) * KSTR + s];
                                    }
                                }
                            }
                            Pv = S2_sh[lane * KSTR + s] - a0 - a1;
                        } else {
#pragma unroll
                            for (int q = 0; q < 6; q++) {
                                unsigned om = W[q];
                                int D0 = 223 - 32 * q + lane;
                                while (om) {
                                    int b = __ffs(om) - 1; om &= om - 1u;
                                    a0 += kpad[(D0 - b) * KSTR + s];
                                    if (om) {
                                        b = __ffs(om) - 1; om &= om - 1u;
                                        a1 += kpad[(D0 - b) * KSTR + s];
                                    }
                                }
                            }
                            Pv = a0 + a1;
                        }
                        Pn_sh[(c + 1) & 1][lane * KSTR + s] = Pv;
                    }
                }
            }
            __syncthreads();
        } else {
            // ---- general fallback: per-thread pre-phase + serial loop ----
            float P = 0.f;
            {
                int t = t0 + fi;
                int uhi = t0 - 1;
                int ulo = t - TNO; if (ulo < 0) ulo = 0;
                if (uhi >= ulo) {
                    int wlo = ulo >> 5;
#pragma unroll
                    for (int q8 = 0; q8 < 8; q8++) {
                        int w = wlo + q8;
                        int bu = w << 5;
                        unsigned valid = 0u;
                        if (bu >= 0 && bu <= uhi) {
                            valid = 0xFFFFFFFFu;
                            if (bu < ulo) valid <<= (ulo - bu);
                            int hb = uhi - bu;
                            if (hb < 31) valid &= ((2u << hb) - 1u);
                        }
                        unsigned om = (valid ? ring[(w & 15) * SUB + fs] : 0u) & valid;
                        int Cw = t - 1 - (w << 5);
                        while (om) {
                            int b = __ffs(om) - 1; om &= om - 1u;
                            P += kpad[(Cw - b) * KSTR + fs];
                        }
                    }
                }
            }
            P_sh[tid] = P;
            base_sh[tid] = fbase;
            __syncthreads();
            if (tid < 16) {
                int ss = tid;
                unsigned myhist = 0u;
                float rho_s = rho_sh[ss];
                for (int ii = 0; ii < CHUNK; ii++) {
                    float Pv2 = P_sh[ii * SUB + ss];
                    float bv = base_sh[ii * SUB + ss];
                    unsigned m = ii ? ((1u << ii) - 1u) : 0u;
                    unsigned om = myhist & m;
                    float intra;
                    if (2 * __popc(om) > ii) {
                        unsigned zm = om ^ m;
                        float a = 0.f;
                        while (zm) { int b = __ffs(zm) - 1; zm &= zm - 1u; a += kpad[b * KSTR + ss]; }
                        intra = Kpre_sh[ii * KSTR + ss] - a;
                    } else {
                        float a = 0.f;
                        while (om) { int b = __ffs(om) - 1; om &= om - 1u; a += kpad[b * KSTR + ss]; }
                        intra = a;
                    }
                    float sub = bv + Pv2 + intra + MBr;
                    bool sp = sub > 0.f;
                    spf[ii * SUB + ss] = sp ? 1.f : 0.f;
                    myhist = (myhist << 1) | (sp ? 1u : 0u);
                    float Ao = A;
                    B = rho_s * (B + Ao);
                    A = rho_s * Ao + (sp ? 1.f : 0.f);
                    float accv = 0.f;
#pragma unroll
                    for (int q = 0; q < 16; q++)
                        accv += cwrow[q] * __shfl_sync(0x0000FFFFu, B, q);
                    MBr = accv;
                }
                ring[((t0 >> 5) & 15) * SUB + ss] = __brev(myhist);
            }
            __syncthreads();
            spk_out[t0 * SUB + tid] = spf[tid];
            float nextbase = 0.f;
            if (c + 1 < NCHUNK) nextbase = g_base[(t0 + CHUNK + fi) * SUB + fs];
            __syncthreads();
            fbase = nextbase;
        }
    }
}

// ---------------- launch ----------------
extern "C" void kernel_launch(void* const* d_in, const int* in_sizes, int n_in,
                              void* d_out, int out_size)
{
    const float* S_e     = (const float*)d_in[0];
    const float* S_i     = (const float*)d_in[1];
    const float* C_den   = (const float*)d_in[2];
    const float* C_syn_e = (const float*)d_in[3];
    const float* C_syn_i = (const float*)d_in[4];
    const float* Tau_e   = (const float*)d_in[5];
    const float* Tau_i   = (const float*)d_in[6];
    const float* W_e     = (const float*)d_in[7];
    const float* W_i     = (const float*)d_in[8];
    const float* D_e     = (const float*)d_in[9];
    const float* D_i     = (const float*)d_in[10];
    const float* Tau_spk = (const float*)d_in[11];
    const float* W_spk   = (const float*)d_in[12];
    const float* W_hist  = (const float*)d_in[13];
    const float* Theta   = (const float*)d_in[14];
    float* out = (float*)d_out;
    float* out_filters = out + T_DATA * SUB;

    k_setup<<<1, 256>>>(C_den, C_syn_e, C_syn_i, Tau_e, Tau_i, W_e, W_i,
                        D_e, D_i, Tau_spk, W_spk, W_hist, out_filters);
    k_segsum<<<T_DATA / SEG_ROWS, 256>>>(S_e, S_i);
    k_conv<<<(T_DATA + TILE_T - 1) / TILE_T, 256>>>(Theta);
    k_scan<<<1, 512>>>(out);
}

// round 12
// speedup vs baseline: 3.0956x; 1.0066x over previous
#include <cuda_runtime.h>
#include <math.h>

#define T_DATA 20000
#define SUB 16
#define TNO 200
#define ENO 2000
#define INO 500
#define CHUNK 32
#define NCHUNK (T_DATA / CHUNK)
#define KSTR 17
#define PI_F 3.14159265358979323846f

// ---------------- device scratch (no allocs allowed) ----------------
__device__ float g_syn_e[T_DATA * SUB];
__device__ float g_syn_i[T_DATA * SUB];
__device__ float g_base[T_DATA * SUB];
__device__ float g_ekT[TNO * SUB];
__device__ float g_ikT[TNO * SUB];
__device__ float g_hkT[TNO * SUB];
__device__ unsigned char g_seg_e[ENO];
__device__ unsigned char g_seg_i[INO];
__device__ float g_cw[SUB * SUB];
__device__ float g_rho[SUB];
__device__ int   g_fast;

#define PAIR_BAR(id) asm volatile("bar.sync %0, %1;" :: "r"(id), "r"(64) : "memory")

// ---------------- K0: setup ----------------
__global__ void k_setup(const float* C_den, const float* C_syn_e, const float* C_syn_i,
                        const float* Tau_e, const float* Tau_i,
                        const float* W_e, const float* W_i,
                        const float* D_e, const float* D_i,
                        const float* Tau_spk, const float* W_spk,
                        const float* W_hist, float* out_filters)
{
    int tid = threadIdx.x;
    for (int idx = tid; idx < SUB * TNO; idx += blockDim.x) {
        int s = idx / TNO, j = idx % TNO;
        float t = (float)j;
        float te  = fmaxf(t - expf(D_e[s]), 0.f);
        float tte = te / expf(Tau_e[s]);
        float ek  = tte * expf(-tte) * expf(W_e[s]);
        float ti  = fmaxf(t - expf(D_i[s]), 0.f);
        float tti = ti / expf(Tau_i[s]);
        float ik  = -tti * expf(-tti) * expf(W_i[s]);
        float tts = t / expf(Tau_spk[s]);
        float sk  = tts * expf(-tts) * expf(W_spk[s]);
        float raw = 4.0f * logf(t + 1.0f);
        float hk = 0.f;
        for (int b = 0; b < 16; b++) {
            float phi = PI_F * 0.5f * (float)b;
            float v = 0.f;
            if (!(raw < phi - PI_F || raw > phi + PI_F))
                v = 0.5f * cosf(raw - phi) + 0.5f;
            hk += W_hist[s * 16 + b] * v;
        }
        g_ekT[j * SUB + s] = ek;
        g_ikT[j * SUB + s] = ik;
        g_hkT[j * SUB + s] = hk;
        out_filters[(0  + s) * TNO + j] = ek;
        out_filters[(16 + s) * TNO + j] = ik;
        out_filters[(32 + s) * TNO + j] = sk;
        out_filters[(48 + s) * TNO + j] = hk;
    }
    for (int e = tid; e < ENO; e += blockDim.x) {
        int seg = 0;
        for (int s = 0; s < SUB; s++) if (C_syn_e[s * ENO + e] > 0.5f) seg = s;
        g_seg_e[e] = (unsigned char)seg;
    }
    for (int e = tid; e < INO; e += blockDim.x) {
        int seg = 0;
        for (int s = 0; s < SUB; s++) if (C_syn_i[s * INO + e] > 0.5f) seg = s;
        g_seg_i[e] = (unsigned char)seg;
    }
    if (tid < SUB) g_rho[tid] = expf(-1.0f / expf(Tau_spk[tid]));
    if (tid < SUB * SUB) {
        int s = tid >> 4, q = tid & 15;
        g_cw[s * SUB + q] = C_den[s * SUB + q] * expf(W_spk[q]) / expf(Tau_spk[q]);
    }
    __syncthreads();
    if (tid == 0) {
        int fast = 1;
        float r0 = g_rho[0];
        for (int s = 1; s < SUB; s++) if (g_rho[s] != r0) fast = 0;
        g_fast = fast;
    }
}

// ---------------- K1: segment sums ----------------
#define SEG_ROWS 4
__global__ void k_segsum(const float* __restrict__ S_e, const float* __restrict__ S_i)
{
    __shared__ unsigned char sege[ENO];
    __shared__ unsigned char segi[INO];
    __shared__ float acc[SEG_ROWS][32];
    int tid = threadIdx.x;
    for (int e = tid; e < ENO; e += blockDim.x) sege[e] = g_seg_e[e];
    for (int e = tid; e < INO; e += blockDim.x) segi[e] = g_seg_i[e];
    if (tid < SEG_ROWS * 32) ((float*)acc)[tid] = 0.f;
    __syncthreads();
    int t0 = blockIdx.x * SEG_ROWS;
    for (int r = 0; r < SEG_ROWS; r++) {
        const float* re = S_e + (size_t)(t0 + r) * ENO;
        for (int e = tid; e < ENO; e += blockDim.x) {
            float v = re[e];
            if (v != 0.f) atomicAdd(&acc[r][sege[e]], v);
        }
        const float* ri = S_i + (size_t)(t0 + r) * INO;
        for (int e = tid; e < INO; e += blockDim.x) {
            float v = ri[e];
            if (v != 0.f) atomicAdd(&acc[r][16 + segi[e]], v);
        }
    }
    __syncthreads();
    if (tid < SEG_ROWS * 32) {
        int r = tid >> 5, q = tid & 31;
        if (q < 16) g_syn_e[(t0 + r) * SUB + q] = acc[r][q];
        else        g_syn_i[(t0 + r) * SUB + (q - 16)] = acc[r][q];
    }
}

// ---------------- K2: causal depthwise FIR + Theta -> base ----------------
#define TILE_T 128
__global__ void k_conv(const float* __restrict__ Theta)
{
    __shared__ float se[(TILE_T + TNO) * SUB];
    __shared__ float si[(TILE_T + TNO) * SUB];
    int t0 = blockIdx.x * TILE_T;
    int tid = threadIdx.x;
    for (int idx = tid; idx < 327 * SUB; idx += blockDim.x) {
        int r = idx / SUB, s = idx % SUB;
        int tt = t0 - 200 + r;
        float ve = 0.f, vi = 0.f;
        if (tt >= 0 && tt < T_DATA) {
            ve = g_syn_e[tt * SUB + s];
            vi = g_syn_i[tt * SUB + s];
        }
        se[idx] = ve;
        si[idx] = vi;
    }
    __syncthreads();
    int s = tid & 15, tg = tid >> 4;
    float th = Theta[s];
    float acc[8];
#pragma unroll
    for (int k = 0; k < 8; k++) acc[k] = th;
    for (int j = 0; j < TNO; j++) {
        float ke = g_ekT[j * SUB + s];
        float ki = g_ikT[j * SUB + s];
#pragma unroll
        for (int k = 0; k < 8; k++) {
            int tl = tg + k * 16;
            int row = tl + 199 - j;
            acc[k] += ke * se[row * SUB + s] + ki * si[row * SUB + s];
        }
    }
#pragma unroll
    for (int k = 0; k < 8; k++) {
        int t = t0 + tg + k * 16;
        if (t < T_DATA) g_base[t * SUB + s] = acc[k];
    }
}

// ---------------- K3: 4-warp 8-step wavefront, parallel-ballot phases ----------------
__global__ void __launch_bounds__(512, 1) k_scan(float* __restrict__ spk_out)
{
    __shared__ float kpad[256 * KSTR];
    __shared__ unsigned ring[16 * SUB];
    __shared__ float inj_sh[CHUNK * SUB];
    __shared__ unsigned balw[2][4][4];      // [buf][round][phase] ballots (A | B<<16)
    __shared__ float lut[4][16][16];
    __shared__ float S2_sh[32 * KSTR];
    __shared__ float Pn_sh[2][32 * KSTR];
    __shared__ float cw_sh[SUB * 17];
    __shared__ float rho_sh[SUB];
    __shared__ float MA0[SUB], MB0[SUB];
    __shared__ float powt[CHUNK + 1], wt[CHUNK + 1];
    __shared__ int fast_sh;
    // fallback-only
    __shared__ float spf[CHUNK * SUB], P_sh[CHUNK * SUB], base_sh[CHUNK * SUB];
    __shared__ float Kpre_sh[32 * KSTR];

    int tid = threadIdx.x;
    int wid = tid >> 5, lane = tid & 31;

    for (int idx = tid; idx < 256 * KSTR; idx += 512) kpad[idx] = 0.f;
    for (int idx = tid; idx < 2 * 32 * KSTR; idx += 512) ((float*)Pn_sh)[idx] = 0.f;
    if (tid < 32) ((unsigned*)balw)[tid] = 0u;
    if (tid < 256) {
        int s = tid >> 4, q = tid & 15;
        cw_sh[s * 17 + q] = g_cw[s * SUB + q];
        ring[tid] = 0u;
    }
    if (tid < SUB) {
        rho_sh[tid] = g_rho[tid];
        MA0[tid] = 0.f; MB0[tid] = 0.f;
    }
    if (tid == 0) fast_sh = g_fast;
    __syncthreads();
    for (int idx = tid; idx < TNO * SUB; idx += 512) {
        int j = idx >> 4, s = idx & 15;
        kpad[j * KSTR + s] = g_hkT[idx];
    }
    if (tid <= CHUNK) {
        float p = powf(rho_sh[0], (float)tid);
        powt[tid] = p;
        wt[tid] = (float)tid * p;
    }
    for (int idx = tid; idx < 1024; idx += 512) {
        int n = idx >> 8, m = (idx >> 4) & 15, ss = idx & 15;
        float v = 0.f;
        for (int b = 0; b < 4; b++)
            if ((m >> b) & 1) v += cw_sh[ss * 17 + 4 * n + b];
        lut[n][m][ss] = v;
    }
    __syncthreads();
    {
        int ii = tid >> 4, ss = tid & 15;
        float suf = 0.f;
        for (int b = ii + 32; b < TNO; b++) suf += kpad[b * KSTR + ss];
        S2_sh[ii * KSTR + ss] = suf;
        float pre = 0.f;
        for (int b = 0; b < ii; b++) pre += kpad[b * KSTR + ss];
        Kpre_sh[ii * KSTR + ss] = pre;
    }
    __syncthreads();

    // fallback state
    float MBr = 0.f, A = 0.f, B = 0.f;
    float cwrow[16];
    if (tid < 16) {
#pragma unroll
        for (int q = 0; q < 16; q++) cwrow[q] = cw_sh[tid * 17 + q];
    }
    const int fi = tid >> 4, fs = tid & 15;
    float fbase = g_base[fi * SUB + fs];

    // chain constants
    const int half = lane >> 4, sc = lane & 15;
    float kcr[7], wtr[7];
#pragma unroll
    for (int d = 0; d < 7; d++) { kcr[d] = kpad[d * KSTR + sc]; wtr[d] = wt[d]; }
    float p32 = powt[CHUNK];
    float invp32 = 1.f / p32;
    float base_r[4], powi[4], wti[4], rpw[4], ipm[4];
    if (wid < 4) {
#pragma unroll
        for (int p = 0; p < 4; p++) {
            int ip = 8 * wid + 2 * p + half;
            powi[p] = powt[ip];
            wti[p] = wt[ip];
            rpw[p] = powt[ip] * invp32;
            ipm[p] = (float)(ip - 32);
            base_r[p] = g_base[ip * SUB + sc];
        }
    }
    const int pns0 = (wid - 8) * 2, pns1 = pns0 + 1;

    for (int c = 0; c < NCHUNK; c++) {
        int t0 = c * CHUNK;

        if (fast_sh) {
            if (wid < 4) {
                // ---- prologue: bP + prev-chunk k applies ----
                float mb = MB0[sc], ma = MA0[sc];
                float bPv[4], acck[4];
#pragma unroll
                for (int p = 0; p < 4; p++) {
                    int ip = 8 * wid + 2 * p + half;
                    bPv[p] = base_r[p] + Pn_sh[c & 1][ip * KSTR + sc] + powi[p] * mb + wti[p] * ma;
                    acck[p] = 0.f;
                }
                {
                    const unsigned (*bp)[4] = balw[(c & 1) ^ 1];
#pragma unroll
                    for (int r = 0; r < 4; r++) {
#pragma unroll
                        for (int ph = 0; ph < 4; ph++) {
                            unsigned bw = bp[r][ph];
                            float fe = (float)((bw >> sc) & 1u);
                            float fo = (float)((bw >> (16 + sc)) & 1u);
                            int ue = 8 * r + 2 * ph;
#pragma unroll
                            for (int p = 0; p < 4; p++) {
                                int de = (8 * wid + 2 * p + half) + 31 - ue;
                                acck[p] += fe * kpad[de * KSTR + sc] + fo * kpad[(de - 1) * KSTR + sc];
                            }
                        }
                    }
                }
                float Qa = 0.f, Qb = 0.f;
                if (wid == 0) {
                    if (half == 0) ring[(c & 15) * SUB + sc] = 0u;
                } else {
                    PAIR_BAR(wid);
                    const unsigned (*bc)[4] = balw[c & 1];
#pragma unroll
                    for (int r = 0; r < 3; r++) if (r < wid) {
#pragma unroll
                        for (int ph = 0; ph < 4; ph++) {
                            unsigned bw = bc[r][ph];
                            float fe = (float)((bw >> sc) & 1u);
                            float fo = (float)((bw >> (16 + sc)) & 1u);
                            int ue = 8 * r + 2 * ph;
                            float je = inj_sh[ue * SUB + sc];
                            float jo = inj_sh[(ue + 1) * SUB + sc];
                            Qa += powt[31 - ue] * je + powt[30 - ue] * jo;
                            Qb += wt[31 - ue] * je + wt[30 - ue] * jo;
#pragma unroll
                            for (int p = 0; p < 4; p++) {
                                int de = (8 * wid + 2 * p + half) - 1 - ue;
                                acck[p] += fe * kpad[de * KSTR + sc] + fo * kpad[(de - 1) * KSTR + sc];
                            }
                        }
                    }
                }
                // ---- 4 in-warp phases (8 steps), parallel hypothesis ballots ----
                unsigned balAv[4], balBv[4];
                float injE[4];
                float inw[4] = {0.f, 0.f, 0.f, 0.f};
#pragma unroll
                for (int p = 0; p < 4; p++) {
                    float sub = bPv[p] + acck[p] + inw[p] + rpw[p] * (ipm[p] * Qa + Qb);
                    // ballot1: low16 = even-step votes, high16 = odd "no-k0" hypothesis
                    unsigned b1 = __ballot_sync(0xFFFFFFFFu, sub > 0.f);
                    // ballot2: high16 = odd "with-k0" hypothesis (low16 unused)
                    unsigned b2 = __ballot_sync(0xFFFFFFFFu, sub + kcr[0] > 0.f);
                    unsigned balA = b1 & 0xFFFFu;
                    unsigned h0 = b1 >> 16, h1 = b2 >> 16;
                    unsigned balB = (balA & h1) | (~balA & h0);
                    balAv[p] = balA; balBv[p] = balB;
                    // dual LUT: both halves compute even & odd inj locally (no shuffle)
                    float injEv = lut[0][balA & 15][sc] + lut[1][(balA >> 4) & 15][sc]
                                + lut[2][(balA >> 8) & 15][sc] + lut[3][(balA >> 12) & 15][sc];
                    float injOd = lut[0][balB & 15][sc] + lut[1][(balB >> 4) & 15][sc]
                                + lut[2][(balB >> 8) & 15][sc] + lut[3][(balB >> 12) & 15][sc];
                    injE[p] = half ? injOd : injEv;
                    if (p < 3) {
                        float fe = (float)((balA >> sc) & 1u);
                        float fo = (float)((balB >> sc) & 1u);
#pragma unroll
                        for (int pp = p + 1; pp < 4; pp++) {
                            const int bd = 2 * (pp - p) - 1;   // 1,3,5
                            float kA = half ? kcr[bd + 1] : kcr[bd];
                            float kB = half ? kcr[bd] : kcr[bd - 1];
                            float wA = half ? wtr[bd + 1] : wtr[bd];
                            float wB = half ? wtr[bd] : wtr[bd - 1];
                            inw[pp] += fe * kA + wA * injEv + fo * kB + wB * injOd;
                        }
                    }
                }
                // ---- publish + release ----
#pragma unroll
                for (int p = 0; p < 4; p++)
                    inj_sh[(8 * wid + 2 * p + half) * SUB + sc] = injE[p];
                if (lane == 0) {
                    balw[c & 1][wid][0] = balAv[0] | (balBv[0] << 16);
                    balw[c & 1][wid][1] = balAv[1] | (balBv[1] << 16);
                    balw[c & 1][wid][2] = balAv[2] | (balBv[2] << 16);
                    balw[c & 1][wid][3] = balAv[3] | (balBv[3] << 16);
                }
                PAIR_BAR(wid + 1);   // bars 1..4 (warp3 releases warp4 for epilogue)
                // ---- post-release ----
                if (half == 0) {
                    unsigned bits = 0u;
#pragma unroll
                    for (int p = 0; p < 4; p++)
                        bits |= (((balAv[p] >> sc) & 1u) << (8 * wid + 2 * p))
                              | (((balBv[p] >> sc) & 1u) << (8 * wid + 2 * p + 1));
                    atomicOr(&ring[(c & 15) * SUB + sc], bits);
                }
#pragma unroll
                for (int p = 0; p < 4; p++) {
                    unsigned myb = half ? balBv[p] : balAv[p];
                    spk_out[(t0 + 8 * wid + 2 * p + half) * SUB + sc] = ((myb >> sc) & 1u) ? 1.f : 0.f;
                }
                if (c + 1 < NCHUNK) {
#pragma unroll
                    for (int p = 0; p < 4; p++)
                        base_r[p] = g_base[(t0 + CHUNK + 8 * wid + 2 * p + half) * SUB + sc];
                }
            } else if (wid == 4) {
                // ---- epilogue warp: MA0/MB0 closed-form update (released by warp3) ----
                PAIR_BAR(4);
                int h = half, scl = sc;
                float sAp = 0.f, sBp = 0.f;
                int u0 = h * 16;
#pragma unroll
                for (int u = 0; u < 16; u++) {
                    float v = inj_sh[(u0 + u) * SUB + scl];
                    sAp += powt[31 - (u0 + u)] * v;
                    sBp += wt[31 - (u0 + u)] * v;
                }
                float sA = sAp + __shfl_xor_sync(0xFFFFFFFFu, sAp, 16);
                float sB = sBp + __shfl_xor_sync(0xFFFFFFFFu, sBp, 16);
                if (h == 0) {
                    float oMA = MA0[scl], oMB = MB0[scl];
                    MA0[scl] = p32 * oMA + sA;
                    MB0[scl] = p32 * oMB + 32.f * p32 * oMA + sB;
                }
            } else if (wid >= 8) {
                // ---- Pn warps: next-chunk pre-history, 2 subunits each ----
                if (c + 1 < NCHUNK) {
                    int wbase = c - 6;
#pragma unroll
                    for (int pass = 0; pass < 2; pass++) {
                        int s = pass ? pns1 : pns0;
                        unsigned W[6];
                        int ones = 0;
#pragma unroll
                        for (int q = 0; q < 6; q++) {
                            int w = wbase + q;
                            unsigned wd = (w >= 0) ? ring[(w & 15) * SUB + s] : 0u;
                            W[q] = wd;
                            ones += __popc(wd);
                        }
                        float a0 = 0.f, a1 = 0.f;
                        float Pv;
                        if (2 * ones > 192) {
#pragma unroll
                            for (int q = 0; q < 6; q++) {
                                unsigned zm = ~W[q];
                                int D0 = 223 - 32 * q + lane;
                                while (zm) {
                                    int b = __ffs(zm) - 1; zm &= zm - 1u;
                                    a0 += kpad[(D0 - b) * KSTR + s];
                                    if (zm) {
                                        b = __ffs(zm) - 1; zm &= zm - 1u;
                                        a1 += kpad[(D0 - b) * KSTR + s];
                                    }
                                }
                            }
                            Pv = S2_sh[lane * KSTR + s] - a0 - a1;
                        } else {
#pragma unroll
                            for (int q = 0; q < 6; q++) {
                                unsigned om = W[q];
                                int D0 = 223 - 32 * q + lane;
                                while (om) {
                                    int b = __ffs(om) - 1; om &= om - 1u;
                                    a0 += kpad[(D0 - b) * KSTR + s];
                                    if (om) {
                                        b = __ffs(om) - 1; om &= om - 1u;
                                        a1 += kpad[(D0 - b) * KSTR + s];
                                    }
                                }
                            }
                            Pv = a0 + a1;
                        }
                        Pn_sh[(c + 1) & 1][lane * KSTR + s] = Pv;
                    }
                }
            }
            __syncthreads();
        } else {
            // ---- general fallback: per-thread pre-phase + serial loop ----
            float P = 0.f;
            {
                int t = t0 + fi;
                int uhi = t0 - 1;
                int ulo = t - TNO; if (ulo < 0) ulo = 0;
                if (uhi >= ulo) {
                    int wlo = ulo >> 5;
#pragma unroll
                    for (int q8 = 0; q8 < 8; q8++) {
                        int w = wlo + q8;
                        int bu = w << 5;
                        unsigned valid = 0u;
                        if (bu >= 0 && bu <= uhi) {
                            valid = 0xFFFFFFFFu;
                            if (bu < ulo) valid <<= (ulo - bu);
                            int hb = uhi - bu;
                            if (hb < 31) valid &= ((2u << hb) - 1u);
                        }
                        unsigned om = (valid ? ring[(w & 15) * SUB + fs] : 0u) & valid;
                        int Cw = t - 1 - (w << 5);
                        while (om) {
                            int b = __ffs(om) - 1; om &= om - 1u;
                            P += kpad[(Cw - b) * KSTR + fs];
                        }
                    }
                }
            }
            P_sh[tid] = P;
            base_sh[tid] = fbase;
            __syncthreads();
            if (tid < 16) {
                int ss = tid;
                unsigned myhist = 0u;
                float rho_s = rho_sh[ss];
                for (int ii = 0; ii < CHUNK; ii++) {
                    float Pv2 = P_sh[ii * SUB + ss];
                    float bv = base_sh[ii * SUB + ss];
                    unsigned m = ii ? ((1u << ii) - 1u) : 0u;
                    unsigned om = myhist & m;
                    float intra;
                    if (2 * __popc(om) > ii) {
                        unsigned zm = om ^ m;
                        float a = 0.f;
                        while (zm) { int b = __ffs(zm) - 1; zm &= zm - 1u; a += kpad[b * KSTR + ss]; }
                        intra = Kpre_sh[ii * KSTR + ss] - a;
                    } else {
                        float a = 0.f;
                        while (om) { int b = __ffs(om) - 1; om &= om - 1u; a += kpad[b * KSTR + ss]; }
                        intra = a;
                    }
                    float sub = bv + Pv2 + intra + MBr;
                    bool sp = sub > 0.f;
                    spf[ii * SUB + ss] = sp ? 1.f : 0.f;
                    myhist = (myhist << 1) | (sp ? 1u : 0u);
                    float Ao = A;
                    B = rho_s * (B + Ao);
                    A = rho_s * Ao + (sp ? 1.f : 0.f);
                    float accv = 0.f;
#pragma unroll
                    for (int q = 0; q < 16; q++)
                        accv += cwrow[q] * __shfl_sync(0x0000FFFFu, B, q);
                    MBr = accv;
                }
                ring[((t0 >> 5) & 15) * SUB + ss] = __brev(myhist);
            }
            __syncthreads();
            spk_out[t0 * SUB + tid] = spf[tid];
            float nextbase = 0.f;
            if (c + 1 < NCHUNK) nextbase = g_base[(t0 + CHUNK + fi) * SUB + fs];
            __syncthreads();
            fbase = nextbase;
        }
    }
}

// ---------------- launch ----------------
extern "C" void kernel_launch(void* const* d_in, const int* in_sizes, int n_in,
                              void* d_out, int out_size)
{
    const float* S_e     = (const float*)d_in[0];
    const float* S_i     = (const float*)d_in[1];
    const float* C_den   = (const float*)d_in[2];
    const float* C_syn_e = (const float*)d_in[3];
    const float* C_syn_i = (const float*)d_in[4];
    const float* Tau_e   = (const float*)d_in[5];
    const float* Tau_i   = (const float*)d_in[6];
    const float* W_e     = (const float*)d_in[7];
    const float* W_i     = (const float*)d_in[8];
    const float* D_e     = (const float*)d_in[9];
    const float* D_i     = (const float*)d_in[10];
    const float* Tau_spk = (const float*)d_in[11];
    const float* W_spk   = (const float*)d_in[12];
    const float* W_hist  = (const float*)d_in[13];
    const float* Theta   = (const float*)d_in[14];
    float* out = (float*)d_out;
    float* out_filters = out + T_DATA * SUB;

    k_setup<<<1, 256>>>(C_den, C_syn_e, C_syn_i, Tau_e, Tau_i, W_e, W_i,
                        D_e, D_i, Tau_spk, W_spk, W_hist, out_filters);
    k_segsum<<<T_DATA / SEG_ROWS, 256>>>(S_e, S_i);
    k_conv<<<(T_DATA + TILE_T - 1) / TILE_T, 256>>>(Theta);
    k_scan<<<1, 512>>>(out);
}

// round 13
// speedup vs baseline: 4.0587x; 1.3112x over previous
#include <cuda_runtime.h>
#include <math.h>

#define T_DATA 20000
#define SUB 16
#define TNO 200
#define ENO 2000
#define INO 500
#define CHUNK 32
#define NCHUNK (T_DATA / CHUNK)
#define KSTR 17
#define KNIB_BYTES (4 * 256 * KSTR * 4)
#define PI_F 3.14159265358979323846f

// ---------------- device scratch (no allocs allowed) ----------------
__device__ float g_syn_e[T_DATA * SUB];
__device__ float g_syn_i[T_DATA * SUB];
__device__ float g_base[T_DATA * SUB];
__device__ float g_ekT[TNO * SUB];
__device__ float g_ikT[TNO * SUB];
__device__ float g_hkT[TNO * SUB];
__device__ unsigned char g_seg_e[ENO];
__device__ unsigned char g_seg_i[INO];
__device__ float g_cw[SUB * SUB];
__device__ float g_rho[SUB];
__device__ int   g_fast;

#define PAIR_BAR(id) asm volatile("bar.sync %0, %1;" :: "r"(id), "r"(64) : "memory")

// ---------------- K0: setup ----------------
__global__ void k_setup(const float* C_den, const float* C_syn_e, const float* C_syn_i,
                        const float* Tau_e, const float* Tau_i,
                        const float* W_e, const float* W_i,
                        const float* D_e, const float* D_i,
                        const float* Tau_spk, const float* W_spk,
                        const float* W_hist, float* out_filters)
{
    int tid = threadIdx.x;
    for (int idx = tid; idx < SUB * TNO; idx += blockDim.x) {
        int s = idx / TNO, j = idx % TNO;
        float t = (float)j;
        float te  = fmaxf(t - expf(D_e[s]), 0.f);
        float tte = te / expf(Tau_e[s]);
        float ek  = tte * expf(-tte) * expf(W_e[s]);
        float ti  = fmaxf(t - expf(D_i[s]), 0.f);
        float tti = ti / expf(Tau_i[s]);
        float ik  = -tti * expf(-tti) * expf(W_i[s]);
        float tts = t / expf(Tau_spk[s]);
        float sk  = tts * expf(-tts) * expf(W_spk[s]);
        float raw = 4.0f * logf(t + 1.0f);
        float hk = 0.f;
        for (int b = 0; b < 16; b++) {
            float phi = PI_F * 0.5f * (float)b;
            float v = 0.f;
            if (!(raw < phi - PI_F || raw > phi + PI_F))
                v = 0.5f * cosf(raw - phi) + 0.5f;
            hk += W_hist[s * 16 + b] * v;
        }
        g_ekT[j * SUB + s] = ek;
        g_ikT[j * SUB + s] = ik;
        g_hkT[j * SUB + s] = hk;
        out_filters[(0  + s) * TNO + j] = ek;
        out_filters[(16 + s) * TNO + j] = ik;
        out_filters[(32 + s) * TNO + j] = sk;
        out_filters[(48 + s) * TNO + j] = hk;
    }
    for (int e = tid; e < ENO; e += blockDim.x) {
        int seg = 0;
        for (int s = 0; s < SUB; s++) if (C_syn_e[s * ENO + e] > 0.5f) seg = s;
        g_seg_e[e] = (unsigned char)seg;
    }
    for (int e = tid; e < INO; e += blockDim.x) {
        int seg = 0;
        for (int s = 0; s < SUB; s++) if (C_syn_i[s * INO + e] > 0.5f) seg = s;
        g_seg_i[e] = (unsigned char)seg;
    }
    if (tid < SUB) g_rho[tid] = expf(-1.0f / expf(Tau_spk[tid]));
    if (tid < SUB * SUB) {
        int s = tid >> 4, q = tid & 15;
        g_cw[s * SUB + q] = C_den[s * SUB + q] * expf(W_spk[q]) / expf(Tau_spk[q]);
    }
    __syncthreads();
    if (tid == 0) {
        int fast = 1;
        float r0 = g_rho[0];
        for (int s = 1; s < SUB; s++) if (g_rho[s] != r0) fast = 0;
        g_fast = fast;
    }
}

// ---------------- K1: segment sums ----------------
#define SEG_ROWS 4
__global__ void k_segsum(const float* __restrict__ S_e, const float* __restrict__ S_i)
{
    __shared__ unsigned char sege[ENO];
    __shared__ unsigned char segi[INO];
    __shared__ float acc[SEG_ROWS][32];
    int tid = threadIdx.x;
    for (int e = tid; e < ENO; e += blockDim.x) sege[e] = g_seg_e[e];
    for (int e = tid; e < INO; e += blockDim.x) segi[e] = g_seg_i[e];
    if (tid < SEG_ROWS * 32) ((float*)acc)[tid] = 0.f;
    __syncthreads();
    int t0 = blockIdx.x * SEG_ROWS;
    for (int r = 0; r < SEG_ROWS; r++) {
        const float* re = S_e + (size_t)(t0 + r) * ENO;
        for (int e = tid; e < ENO; e += blockDim.x) {
            float v = re[e];
            if (v != 0.f) atomicAdd(&acc[r][sege[e]], v);
        }
        const float* ri = S_i + (size_t)(t0 + r) * INO;
        for (int e = tid; e < INO; e += blockDim.x) {
            float v = ri[e];
            if (v != 0.f) atomicAdd(&acc[r][16 + segi[e]], v);
        }
    }
    __syncthreads();
    if (tid < SEG_ROWS * 32) {
        int r = tid >> 5, q = tid & 31;
        if (q < 16) g_syn_e[(t0 + r) * SUB + q] = acc[r][q];
        else        g_syn_i[(t0 + r) * SUB + (q - 16)] = acc[r][q];
    }
}

// ---------------- K2: causal depthwise FIR + Theta -> base ----------------
#define TILE_T 128
__global__ void k_conv(const float* __restrict__ Theta)
{
    __shared__ float se[(TILE_T + TNO) * SUB];
    __shared__ float si[(TILE_T + TNO) * SUB];
    int t0 = blockIdx.x * TILE_T;
    int tid = threadIdx.x;
    for (int idx = tid; idx < 327 * SUB; idx += blockDim.x) {
        int r = idx / SUB, s = idx % SUB;
        int tt = t0 - 200 + r;
        float ve = 0.f, vi = 0.f;
        if (tt >= 0 && tt < T_DATA) {
            ve = g_syn_e[tt * SUB + s];
            vi = g_syn_i[tt * SUB + s];
        }
        se[idx] = ve;
        si[idx] = vi;
    }
    __syncthreads();
    int s = tid & 15, tg = tid >> 4;
    float th = Theta[s];
    float acc[8];
#pragma unroll
    for (int k = 0; k < 8; k++) acc[k] = th;
    for (int j = 0; j < TNO; j++) {
        float ke = g_ekT[j * SUB + s];
        float ki = g_ikT[j * SUB + s];
#pragma unroll
        for (int k = 0; k < 8; k++) {
            int tl = tg + k * 16;
            int row = tl + 199 - j;
            acc[k] += ke * se[row * SUB + s] + ki * si[row * SUB + s];
        }
    }
#pragma unroll
    for (int k = 0; k < 8; k++) {
        int t = t0 + tg + k * 16;
        if (t < T_DATA) g_base[t * SUB + s] = acc[k];
    }
}

// ---------------- K3: 4-warp 8-step wavefront; Pn via 2-bit-pair LUT ----------------
__global__ void __launch_bounds__(512, 1) k_scan(float* __restrict__ spk_out)
{
    extern __shared__ float knib[];         // [state][d][s] stride 17: b0*k[d]+b1*k[d-1]
    __shared__ float kpad[256 * KSTR];
    __shared__ unsigned ring[16 * SUB];
    __shared__ float inj_sh[CHUNK * SUB];
    __shared__ unsigned balw[2][4][4];      // [buf][round][phase] ballots (A | B<<16)
    __shared__ float lut[4][16][16];
    __shared__ float S2_sh[32 * KSTR];
    __shared__ float Pn_sh[2][32 * KSTR];
    __shared__ float cw_sh[SUB * 17];
    __shared__ float rho_sh[SUB];
    __shared__ float MA0[SUB], MB0[SUB];
    __shared__ float powt[CHUNK + 1], wt[CHUNK + 1];
    __shared__ int fast_sh;
    // fallback-only
    __shared__ float spf[CHUNK * SUB], P_sh[CHUNK * SUB], base_sh[CHUNK * SUB];
    __shared__ float Kpre_sh[32 * KSTR];

    int tid = threadIdx.x;
    int wid = tid >> 5, lane = tid & 31;

    for (int idx = tid; idx < 256 * KSTR; idx += 512) kpad[idx] = 0.f;
    for (int idx = tid; idx < 2 * 32 * KSTR; idx += 512) ((float*)Pn_sh)[idx] = 0.f;
    if (tid < 32) ((unsigned*)balw)[tid] = 0u;
    if (tid < 256) {
        int s = tid >> 4, q = tid & 15;
        cw_sh[s * 17 + q] = g_cw[s * SUB + q];
        ring[tid] = 0u;
    }
    if (tid < SUB) {
        rho_sh[tid] = g_rho[tid];
        MA0[tid] = 0.f; MB0[tid] = 0.f;
    }
    if (tid == 0) fast_sh = g_fast;
    __syncthreads();
    for (int idx = tid; idx < TNO * SUB; idx += 512) {
        int j = idx >> 4, s = idx & 15;
        kpad[j * KSTR + s] = g_hkT[idx];
    }
    if (tid <= CHUNK) {
        float p = powf(rho_sh[0], (float)tid);
        powt[tid] = p;
        wt[tid] = (float)tid * p;
    }
    for (int idx = tid; idx < 1024; idx += 512) {
        int n = idx >> 8, m = (idx >> 4) & 15, ss = idx & 15;
        float v = 0.f;
        for (int b = 0; b < 4; b++)
            if ((m >> b) & 1) v += cw_sh[ss * 17 + 4 * n + b];
        lut[n][m][ss] = v;
    }
    __syncthreads();
    {
        int ii = tid >> 4, ss = tid & 15;
        float suf = 0.f;
        for (int b = ii + 32; b < TNO; b++) suf += kpad[b * KSTR + ss];
        S2_sh[ii * KSTR + ss] = suf;
        float pre = 0.f;
        for (int b = 0; b < ii; b++) pre += kpad[b * KSTR + ss];
        Kpre_sh[ii * KSTR + ss] = pre;
    }
    // 2-bit-pair LUT (needs kpad)
    for (int idx = tid; idx < 4 * 256 * 16; idx += 512) {
        int st = idx >> 12, d = (idx >> 4) & 255, s = idx & 15;
        float v = 0.f;
        if (st & 1) v += kpad[d * KSTR + s];
        if ((st & 2) && d >= 1) v += kpad[(d - 1) * KSTR + s];
        knib[(st * 256 + d) * KSTR + s] = v;
    }
    __syncthreads();

    // fallback state
    float MBr = 0.f, A = 0.f, B = 0.f;
    float cwrow[16];
    if (tid < 16) {
#pragma unroll
        for (int q = 0; q < 16; q++) cwrow[q] = cw_sh[tid * 17 + q];
    }
    const int fi = tid >> 4, fs = tid & 15;
    float fbase = g_base[fi * SUB + fs];

    // chain constants
    const int half = lane >> 4, sc = lane & 15;
    float kcr[7], wtr[7];
#pragma unroll
    for (int d = 0; d < 7; d++) { kcr[d] = kpad[d * KSTR + sc]; wtr[d] = wt[d]; }
    float p32 = powt[CHUNK];
    float invp32 = 1.f / p32;
    float base_r[4], powi[4], wti[4], rpw[4], ipm[4];
    if (wid < 4) {
#pragma unroll
        for (int p = 0; p < 4; p++) {
            int ip = 8 * wid + 2 * p + half;
            powi[p] = powt[ip];
            wti[p] = wt[ip];
            rpw[p] = powt[ip] * invp32;
            ipm[p] = (float)(ip - 32);
            base_r[p] = g_base[ip * SUB + sc];
        }
    }
    const int pns0 = (wid - 8) * 2, pns1 = pns0 + 1;

    for (int c = 0; c < NCHUNK; c++) {
        int t0 = c * CHUNK;

        if (fast_sh) {
            if (wid < 4) {
                // ---- prologue: bP + prev-chunk k applies ----
                float mb = MB0[sc], ma = MA0[sc];
                float bPv[4], acck[4];
#pragma unroll
                for (int p = 0; p < 4; p++) {
                    int ip = 8 * wid + 2 * p + half;
                    bPv[p] = base_r[p] + Pn_sh[c & 1][ip * KSTR + sc] + powi[p] * mb + wti[p] * ma;
                    acck[p] = 0.f;
                }
                {
                    const unsigned (*bp)[4] = balw[(c & 1) ^ 1];
#pragma unroll
                    for (int r = 0; r < 4; r++) {
#pragma unroll
                        for (int ph = 0; ph < 4; ph++) {
                            unsigned bw = bp[r][ph];
                            float fe = (float)((bw >> sc) & 1u);
                            float fo = (float)((bw >> (16 + sc)) & 1u);
                            int ue = 8 * r + 2 * ph;
#pragma unroll
                            for (int p = 0; p < 4; p++) {
                                int de = (8 * wid + 2 * p + half) + 31 - ue;
                                acck[p] += fe * kpad[de * KSTR + sc] + fo * kpad[(de - 1) * KSTR + sc];
                            }
                        }
                    }
                }
                float Qa = 0.f, Qb = 0.f;
                if (wid == 0) {
                    if (half == 0) ring[(c & 15) * SUB + sc] = 0u;
                } else {
                    PAIR_BAR(wid);
                    const unsigned (*bc)[4] = balw[c & 1];
#pragma unroll
                    for (int r = 0; r < 3; r++) if (r < wid) {
#pragma unroll
                        for (int ph = 0; ph < 4; ph++) {
                            unsigned bw = bc[r][ph];
                            float fe = (float)((bw >> sc) & 1u);
                            float fo = (float)((bw >> (16 + sc)) & 1u);
                            int ue = 8 * r + 2 * ph;
                            float je = inj_sh[ue * SUB + sc];
                            float jo = inj_sh[(ue + 1) * SUB + sc];
                            Qa += powt[31 - ue] * je + powt[30 - ue] * jo;
                            Qb += wt[31 - ue] * je + wt[30 - ue] * jo;
#pragma unroll
                            for (int p = 0; p < 4; p++) {
                                int de = (8 * wid + 2 * p + half) - 1 - ue;
                                acck[p] += fe * kpad[de * KSTR + sc] + fo * kpad[(de - 1) * KSTR + sc];
                            }
                        }
                    }
                }
                // ---- 4 in-warp phases (8 steps), parallel hypothesis ballots ----
                unsigned balAv[4], balBv[4];
                float injE[4];
                float inw[4] = {0.f, 0.f, 0.f, 0.f};
#pragma unroll
                for (int p = 0; p < 4; p++) {
                    float sub = bPv[p] + acck[p] + inw[p] + rpw[p] * (ipm[p] * Qa + Qb);
                    unsigned b1 = __ballot_sync(0xFFFFFFFFu, sub > 0.f);
                    unsigned b2 = __ballot_sync(0xFFFFFFFFu, sub + kcr[0] > 0.f);
                    unsigned balA = b1 & 0xFFFFu;
                    unsigned h0 = b1 >> 16, h1 = b2 >> 16;
                    unsigned balB = (balA & h1) | (~balA & h0);
                    balAv[p] = balA; balBv[p] = balB;
                    float injEv = lut[0][balA & 15][sc] + lut[1][(balA >> 4) & 15][sc]
                                + lut[2][(balA >> 8) & 15][sc] + lut[3][(balA >> 12) & 15][sc];
                    float injOd = lut[0][balB & 15][sc] + lut[1][(balB >> 4) & 15][sc]
                                + lut[2][(balB >> 8) & 15][sc] + lut[3][(balB >> 12) & 15][sc];
                    injE[p] = half ? injOd : injEv;
                    if (p < 3) {
                        float fe = (float)((balA >> sc) & 1u);
                        float fo = (float)((balB >> sc) & 1u);
#pragma unroll
                        for (int pp = p + 1; pp < 4; pp++) {
                            const int bd = 2 * (pp - p) - 1;   // 1,3,5
                            float kA = half ? kcr[bd + 1] : kcr[bd];
                            float kB = half ? kcr[bd] : kcr[bd - 1];
                            float wA = half ? wtr[bd + 1] : wtr[bd];
                            float wB = half ? wtr[bd] : wtr[bd - 1];
                            inw[pp] += fe * kA + wA * injEv + fo * kB + wB * injOd;
                        }
                    }
                }
                // ---- publish + release ----
#pragma unroll
                for (int p = 0; p < 4; p++)
                    inj_sh[(8 * wid + 2 * p + half) * SUB + sc] = injE[p];
                if (lane == 0) {
                    balw[c & 1][wid][0] = balAv[0] | (balBv[0] << 16);
                    balw[c & 1][wid][1] = balAv[1] | (balBv[1] << 16);
                    balw[c & 1][wid][2] = balAv[2] | (balBv[2] << 16);
                    balw[c & 1][wid][3] = balAv[3] | (balBv[3] << 16);
                }
                PAIR_BAR(wid + 1);   // bars 1..4 (warp3 releases warp4 for epilogue)
                // ---- post-release ----
                if (half == 0) {
                    unsigned bits = 0u;
#pragma unroll
                    for (int p = 0; p < 4; p++)
                        bits |= (((balAv[p] >> sc) & 1u) << (8 * wid + 2 * p))
                              | (((balBv[p] >> sc) & 1u) << (8 * wid + 2 * p + 1));
                    atomicOr(&ring[(c & 15) * SUB + sc], bits);
                }
#pragma unroll
                for (int p = 0; p < 4; p++) {
                    unsigned myb = half ? balBv[p] : balAv[p];
                    spk_out[(t0 + 8 * wid + 2 * p + half) * SUB + sc] = ((myb >> sc) & 1u) ? 1.f : 0.f;
                }
                if (c + 1 < NCHUNK) {
#pragma unroll
                    for (int p = 0; p < 4; p++)
                        base_r[p] = g_base[(t0 + CHUNK + 8 * wid + 2 * p + half) * SUB + sc];
                }
            } else if (wid == 4) {
                // ---- epilogue warp: MA0/MB0 closed-form update (released by warp3) ----
                PAIR_BAR(4);
                int h = half, scl = sc;
                float sAp = 0.f, sBp = 0.f;
                int u0 = h * 16;
#pragma unroll
                for (int u = 0; u < 16; u++) {
                    float v = inj_sh[(u0 + u) * SUB + scl];
                    sAp += powt[31 - (u0 + u)] * v;
                    sBp += wt[31 - (u0 + u)] * v;
                }
                float sA = sAp + __shfl_xor_sync(0xFFFFFFFFu, sAp, 16);
                float sB = sBp + __shfl_xor_sync(0xFFFFFFFFu, sBp, 16);
                if (h == 0) {
                    float oMA = MA0[scl], oMB = MB0[scl];
                    MA0[scl] = p32 * oMA + sA;
                    MB0[scl] = p32 * oMB + 32.f * p32 * oMA + sB;
                }
            } else if (wid >= 8) {
                // ---- Pn warps: 3-way adaptive (ones-scan / zeros-scan / pair-LUT) ----
                if (c + 1 < NCHUNK) {
                    int wbase = c - 6;
#pragma unroll
                    for (int pass = 0; pass < 2; pass++) {
                        int s = pass ? pns1 : pns0;
                        unsigned W[6];
                        int ones = 0;
#pragma unroll
                        for (int q = 0; q < 6; q++) {
                            int w = wbase + q;
                            unsigned wd = (w >= 0) ? ring[(w & 15) * SUB + s] : 0u;
                            W[q] = wd;
                            ones += __popc(wd);
                        }
                        float Pv;
                        if (ones >= 168) {
                            float a0 = 0.f, a1 = 0.f;
#pragma unroll
                            for (int q = 0; q < 6; q++) {
                                unsigned zm = ~W[q];
                                int D0 = 223 - 32 * q + lane;
                                while (zm) {
                                    int b = __ffs(zm) - 1; zm &= zm - 1u;
                                    a0 += kpad[(D0 - b) * KSTR + s];
                                    if (zm) {
                                        b = __ffs(zm) - 1; zm &= zm - 1u;
                                        a1 += kpad[(D0 - b) * KSTR + s];
                                    }
                                }
                            }
                            Pv = S2_sh[lane * KSTR + s] - a0 - a1;
                        } else if (ones <= 24) {
                            float a0 = 0.f, a1 = 0.f;
#pragma unroll
                            for (int q = 0; q < 6; q++) {
                                unsigned om = W[q];
                                int D0 = 223 - 32 * q + lane;
                                while (om) {
                                    int b = __ffs(om) - 1; om &= om - 1u;
                                    a0 += kpad[(D0 - b) * KSTR + s];
                                    if (om) {
                                        b = __ffs(om) - 1; om &= om - 1u;
                                        a1 += kpad[(D0 - b) * KSTR + s];
                                    }
                                }
                            }
                            Pv = a0 + a1;
                        } else {
                            // pair-LUT: fixed 96 uniform iterations, skip zero pairs
                            float a0 = 0.f, a1 = 0.f;
#pragma unroll
                            for (int q = 0; q < 6; q++) {
                                unsigned Wq = W[q];
                                int D0 = 223 - 32 * q + lane;
#pragma unroll
                                for (int jp = 0; jp < 16; jp += 2) {
                                    unsigned st0 = (Wq >> (2 * jp)) & 3u;
                                    unsigned st1 = (Wq >> (2 * jp + 2)) & 3u;
                                    if (st0) a0 += knib[(st0 * 256 + (D0 - 2 * jp)) * KSTR + s];
                                    if (st1) a1 += knib[(st1 * 256 + (D0 - 2 * jp - 2)) * KSTR + s];
                                }
                            }
                            Pv = a0 + a1;
                        }
                        Pn_sh[(c + 1) & 1][lane * KSTR + s] = Pv;
                    }
                }
            }
            __syncthreads();
        } else {
            // ---- general fallback: per-thread pre-phase + serial loop ----
            float P = 0.f;
            {
                int t = t0 + fi;
                int uhi = t0 - 1;
                int ulo = t - TNO; if (ulo < 0) ulo = 0;
                if (uhi >= ulo) {
                    int wlo = ulo >> 5;
#pragma unroll
                    for (int q8 = 0; q8 < 8; q8++) {
                        int w = wlo + q8;
                        int bu = w << 5;
                        unsigned valid = 0u;
                        if (bu >= 0 && bu <= uhi) {
                            valid = 0xFFFFFFFFu;
                            if (bu < ulo) valid <<= (ulo - bu);
                            int hb = uhi - bu;
                            if (hb < 31) valid &= ((2u << hb) - 1u);
                        }
                        unsigned om = (valid ? ring[(w & 15) * SUB + fs] : 0u) & valid;
                        int Cw = t - 1 - (w << 5);
                        while (om) {
                            int b = __ffs(om) - 1; om &= om - 1u;
                            P += kpad[(Cw - b) * KSTR + fs];
                        }
                    }
                }
            }
            P_sh[tid] = P;
            base_sh[tid] = fbase;
            __syncthreads();
            if (tid < 16) {
                int ss = tid;
                unsigned myhist = 0u;
                float rho_s = rho_sh[ss];
                for (int ii = 0; ii < CHUNK; ii++) {
                    float Pv2 = P_sh[ii * SUB + ss];
                    float bv = base_sh[ii * SUB + ss];
                    unsigned m = ii ? ((1u << ii) - 1u) : 0u;
                    unsigned om = myhist & m;
                    float intra;
                    if (2 * __popc(om) > ii) {
                        unsigned zm = om ^ m;
                        float a = 0.f;
                        while (zm) { int b = __ffs(zm) - 1; zm &= zm - 1u; a += kpad[b * KSTR + ss]; }
                        intra = Kpre_sh[ii * KSTR + ss] - a;
                    } else {
                        float a = 0.f;
                        while (om) { int b = __ffs(om) - 1; om &= om - 1u; a += kpad[b * KSTR + ss]; }
                        intra = a;
                    }
                    float sub = bv + Pv2 + intra + MBr;
                    bool sp = sub > 0.f;
                    spf[ii * SUB + ss] = sp ? 1.f : 0.f;
                    myhist = (myhist << 1) | (sp ? 1u : 0u);
                    float Ao = A;
                    B = rho_s * (B + Ao);
                    A = rho_s * Ao + (sp ? 1.f : 0.f);
                    float accv = 0.f;
#pragma unroll
                    for (int q = 0; q < 16; q++)
                        accv += cwrow[q] * __shfl_sync(0x0000FFFFu, B, q);
                    MBr = accv;
                }
                ring[((t0 >> 5) & 15) * SUB + ss] = __brev(myhist);
            }
            __syncthreads();
            spk_out[t0 * SUB + tid] = spf[tid];
            float nextbase = 0.f;
            if (c + 1 < NCHUNK) nextbase = g_base[(t0 + CHUNK + fi) * SUB + fs];
            __syncthreads();
            fbase = nextbase;
        }
    }
}

// ---------------- launch ----------------
extern "C" void kernel_launch(void* const* d_in, const int* in_sizes, int n_in,
                              void* d_out, int out_size)
{
    const float* S_e     = (const float*)d_in[0];
    const float* S_i     = (const float*)d_in[1];
    const float* C_den   = (const float*)d_in[2];
    const float* C_syn_e = (const float*)d_in[3];
    const float* C_syn_i = (const float*)d_in[4];
    const float* Tau_e   = (const float*)d_in[5];
    const float* Tau_i   = (const float*)d_in[6];
    const float* W_e     = (const float*)d_in[7];
    const float* W_i     = (const float*)d_in[8];
    const float* D_e     = (const float*)d_in[9];
    const float* D_i     = (const float*)d_in[10];
    const float* Tau_spk = (const float*)d_in[11];
    const float* W_spk   = (const float*)d_in[12];
    const float* W_hist  = (const float*)d_in[13];
    const float* Theta   = (const float*)d_in[14];
    float* out = (float*)d_out;
    float* out_filters = out + T_DATA * SUB;

    cudaFuncSetAttribute(k_scan, cudaFuncAttributeMaxDynamicSharedMemorySize, KNIB_BYTES);

    k_setup<<<1, 256>>>(C_den, C_syn_e, C_syn_i, Tau_e, Tau_i, W_e, W_i,
                        D_e, D_i, Tau_spk, W_spk, W_hist, out_filters);
    k_segsum<<<T_DATA / SEG_ROWS, 256>>>(S_e, S_i);
    k_conv<<<(T_DATA + TILE_T - 1) / TILE_T, 256>>>(Theta);
    k_scan<<<1, 512, KNIB_BYTES>>>(out);
}